// round 7
// baseline (speedup 1.0000x reference)
#include <cuda_runtime.h>
#include <cstdint>

// MultiHeadAttention_45732811768295 — fp32 FFMA2 with k-pair vectorization (R6).
//   prep    : transpose Wq/Wk/Wv -> g_wT[c][k]; fold+transpose Wo -> g_weffT[m][d]
//   qkv     : q/k/v = X @ W + b   (k-pair, cp.async double buffer, 128x64 tiles)
//   attn    : fixed-max flash softmax(QK^T/8)V, k-pair GEMMs, deferred l-reduce
//   outproj : out = ctx @ Weff + bo (k-pair, 64x128 tiles)

#define B_  8
#define S_  2048
#define DM  1024
#define HD  64
#define ROWS_TOT (B_ * S_)   // 16384

typedef unsigned long long u64;

__device__ __forceinline__ void fma2(u64 &d, u64 a, u64 b) {
    asm("fma.rn.f32x2 %0, %1, %2, %0;" : "+l"(d) : "l"(a), "l"(b));
}
__device__ __forceinline__ float2 unpk2(u64 v) {
    float2 f; asm("mov.b64 {%0,%1}, %2;" : "=f"(f.x), "=f"(f.y) : "l"(v)); return f;
}
__device__ __forceinline__ void cp16(uint32_t saddr, const void* g) {
    asm volatile("cp.async.cg.shared.global [%0], [%1], 16;" :: "r"(saddr), "l"(g));
}
#define CP_COMMIT() asm volatile("cp.async.commit_group;")
#define CP_WAIT1()  asm volatile("cp.async.wait_group 1;")
#define CP_WAIT0()  asm volatile("cp.async.wait_group 0;")

// Scratch (device globals; runtime allocation forbidden)
__device__ float g_q[ROWS_TOT * HD];
__device__ float g_k[ROWS_TOT * HD];
__device__ float g_v[ROWS_TOT * HD];
__device__ float g_ctx[ROWS_TOT * HD];
__device__ float g_wT[3 * HD * DM];    // [w][c][k]  k contiguous
__device__ float g_weffT[DM * HD];     // [m][d]     d contiguous

// ---------------------------------------------------------------------------
// 0) prep: weight transposes + Wo head-fold.  262144 threads total.
// ---------------------------------------------------------------------------
__global__ void prep_kernel(const float* __restrict__ Wq, const float* __restrict__ Wk,
                            const float* __restrict__ Wv, const float* __restrict__ Wo)
{
    int idx = blockIdx.x * 256 + threadIdx.x;
    if (idx < 3 * HD * DM) {
        int w = idx / (HD * DM);
        int r = idx % (HD * DM);
        int k = r >> 6, c = r & 63;               // c fastest -> coalesced reads
        const float* W = (w == 0) ? Wq : (w == 1) ? Wk : Wv;
        g_wT[w * HD * DM + c * DM + k] = W[k * HD + c];
    } else {
        int r = idx - 3 * HD * DM;                // 0..65535
        int d = r >> 10, m = r & 1023;            // m fastest -> coalesced reads
        float s = 0.f;
#pragma unroll
        for (int h = 0; h < 16; h++) s += Wo[(h * 64 + d) * DM + m];
        g_weffT[m * HD + d] = s;
    }
}

// ---------------------------------------------------------------------------
// 1) QKV projection (k-pair).  Block 128 rows x 64 cols, Ktile 32, 256 thr.
//    Thread tile 4x8: ty=tid>>3 (32) rows ty*4..+3; tx=tid&7, cols tx+8j.
//    cp.async double buffer, 2 syncs/iter.
// ---------------------------------------------------------------------------
#define QKV_SMEM_BYTES ((2*128*36 + 2*64*36) * 4)   // 55296

__global__ __launch_bounds__(256, 2) void qkv_kernel(
    const float* __restrict__ in_q, const float* __restrict__ in_k, const float* __restrict__ in_v,
    const float* __restrict__ bq, const float* __restrict__ bk, const float* __restrict__ bv)
{
    extern __shared__ float sq[];
    float* As = sq;                   // [2][128][36]
    float* Bs = sq + 2 * 128 * 36;    // [2][64][36]

    const float* X; const float* bias; float* out;
    if (blockIdx.z == 0)      { X = in_q; bias = bq; out = g_q; }
    else if (blockIdx.z == 1) { X = in_k; bias = bk; out = g_k; }
    else                      { X = in_v; bias = bv; out = g_v; }
    const float* wT = g_wT + blockIdx.z * HD * DM;

    const int tid = threadIdx.x;
    const int ty = tid >> 3;          // 0..31 -> rows ty*4..+3
    const int tx = tid & 7;           // cols tx + 8j
    const int rowBase = blockIdx.x * 128;

    const float4* X4  = (const float4*)X;
    const float4* wT4 = (const float4*)wT;

    const uint32_t sA = (uint32_t)__cvta_generic_to_shared(As);
    const uint32_t sB = (uint32_t)__cvta_generic_to_shared(Bs);

    // per-thread cp.async coordinates
    int aR[4], aK[4];
#pragma unroll
    for (int l = 0; l < 4; l++) { int i4 = tid + l * 256; aR[l] = i4 >> 3; aK[l] = i4 & 7; }
    int bC[2], bK[2];
#pragma unroll
    for (int l = 0; l < 2; l++) { int i4 = tid + l * 256; bC[l] = i4 >> 3; bK[l] = i4 & 7; }

    auto issue = [&](int kt, int buf) {
        const int kb4 = kt * 8;
#pragma unroll
        for (int l = 0; l < 4; l++)
            cp16(sA + (buf * 128 * 9 + aR[l] * 9 + aK[l]) * 16,
                 &X4[(rowBase + aR[l]) * 256 + kb4 + aK[l]]);
#pragma unroll
        for (int l = 0; l < 2; l++)
            cp16(sB + (buf * 64 * 9 + bC[l] * 9 + bK[l]) * 16,
                 &wT4[bC[l] * 256 + kb4 + bK[l]]);
    };

    issue(0, 0); CP_COMMIT();

    u64 acc[4][8];
#pragma unroll
    for (int i = 0; i < 4; i++)
#pragma unroll
        for (int j = 0; j < 8; j++) acc[i][j] = 0ull;

    for (int kt = 0; kt < 32; kt++) {
        const int buf = kt & 1;
        if (kt + 1 < 32) { issue(kt + 1, buf ^ 1); CP_COMMIT(); CP_WAIT1(); }
        else             { CP_WAIT0(); }
        __syncthreads();                       // tile kt visible to all

        const ulonglong2* A2 = (const ulonglong2*)(As + buf * 128 * 36);
        const ulonglong2* B2 = (const ulonglong2*)(Bs + buf * 64 * 36);
#pragma unroll
        for (int k4 = 0; k4 < 8; k4++) {
            ulonglong2 av[4];
#pragma unroll
            for (int i = 0; i < 4; i++) av[i] = A2[(ty * 4 + i) * 9 + k4];
#pragma unroll
            for (int j = 0; j < 8; j++) {
                ulonglong2 bv = B2[(tx + 8 * j) * 9 + k4];
#pragma unroll
                for (int i = 0; i < 4; i++) {
                    fma2(acc[i][j], av[i].x, bv.x);
                    fma2(acc[i][j], av[i].y, bv.y);
                }
            }
        }
        __syncthreads();                       // done reading buf before reuse
    }

    float bias_c[8];
#pragma unroll
    for (int j = 0; j < 8; j++) bias_c[j] = bias[tx + 8 * j];
#pragma unroll
    for (int i = 0; i < 4; i++) {
        const int row = rowBase + ty * 4 + i;
#pragma unroll
        for (int j = 0; j < 8; j++) {
            float2 t = unpk2(acc[i][j]);
            out[row * 64 + tx + 8 * j] = t.x + t.y + bias_c[j];
        }
    }
}

// ---------------------------------------------------------------------------
// 2) Attention (k-pair both GEMMs, fixed-max softmax, deferred l-reduce).
//    q-tile 32 rows, k-tile 64.  256 threads: ty=tid>>4 (16) x ii=2 rows,
//    tx=tid&15 x jj=4 (cols tx+16j).  3 blocks/SM.
// ---------------------------------------------------------------------------
#define ATTN_SMEM_BYTES ((32*68 + 64*68 + 64*68 + 32*68) * 4)   // 52224

__global__ __launch_bounds__(256, 3) void attn_kernel()
{
    extern __shared__ float sa[];
    float* Qs  = sa;                  // [32][68]  natural [i][d]
    float* Ks  = Qs + 32 * 68;        // [64][68]  natural [j][d]
    float* VsT = Ks + 64 * 68;        // [64][68]  transposed [d][j]
    float* Ps  = VsT + 64 * 68;       // [32][68]  natural [i][j]

    const int b   = blockIdx.y;
    const int qt  = blockIdx.x;
    const int tid = threadIdx.x;
    const int ty  = tid >> 4;
    const int tx  = tid & 15;

    const float4* Qg4 = (const float4*)(g_q + (b * S_ + qt * 32) * HD);
    const float*  Kg  = g_k + b * S_ * HD;
    const float*  Vg  = g_v + b * S_ * HD;

    float4* Qs4 = (float4*)Qs;        // row stride 17
    float4* Ks4 = (float4*)Ks;

    // Q tile: 512 float4
#pragma unroll
    for (int l = 0; l < 2; l++) {
        int i4 = tid + l * 256;
        Qs4[(i4 >> 4) * 17 + (i4 & 15)] = Qg4[i4];
    }

    u64 o2[2][4];
    float lsum[2] = {0.f, 0.f};
#pragma unroll
    for (int i = 0; i < 2; i++)
#pragma unroll
        for (int j = 0; j < 4; j++) o2[i][j] = 0ull;

    const ulonglong2* Q2 = (const ulonglong2*)Qs;
    const ulonglong2* K2 = (const ulonglong2*)Ks;
    const ulonglong2* V2 = (const ulonglong2*)VsT;
    const ulonglong2* P2 = (const ulonglong2*)Ps;

    for (int kt = 0; kt < 32; kt++) {
        const float4* Kt4 = (const float4*)(Kg + kt * 64 * HD);
        const float4* Vt4 = (const float4*)(Vg + kt * 64 * HD);
#pragma unroll
        for (int l = 0; l < 4; l++) {
            int i4 = tid + l * 256;
            // K natural copy (coalesced LDG, conflict-free STS.128)
            Ks4[(i4 >> 4) * 17 + (i4 & 15)] = Kt4[i4];
            // V transpose (j-consecutive lanes -> conflict-free STS.32)
            int d4 = i4 >> 6, j = i4 & 63;
            float4 v = Vt4[j * 16 + d4];
            VsT[(4 * d4 + 0) * 68 + j] = v.x;
            VsT[(4 * d4 + 1) * 68 + j] = v.y;
            VsT[(4 * d4 + 2) * 68 + j] = v.z;
            VsT[(4 * d4 + 3) * 68 + j] = v.w;
        }
        __syncthreads();

        // S = Q K^T (k-pair over d; no packs, no dups)
        u64 s2[2][4];
#pragma unroll
        for (int i = 0; i < 2; i++)
#pragma unroll
            for (int j = 0; j < 4; j++) s2[i][j] = 0ull;

#pragma unroll
        for (int d4 = 0; d4 < 16; d4++) {
            ulonglong2 av[2];
#pragma unroll
            for (int i = 0; i < 2; i++) av[i] = Q2[(ty * 2 + i) * 17 + d4];
#pragma unroll
            for (int j = 0; j < 4; j++) {
                ulonglong2 bv = K2[(tx + 16 * j) * 17 + d4];
#pragma unroll
                for (int i = 0; i < 2; i++) {
                    fma2(s2[i][j], av[i].x, bv.x);
                    fma2(s2[i][j], av[i].y, bv.y);
                }
            }
        }

        // fixed-max softmax: p = exp(s/8); accumulate partial row sums
#pragma unroll
        for (int i = 0; i < 2; i++) {
#pragma unroll
            for (int j = 0; j < 4; j++) {
                float2 t = unpk2(s2[i][j]);
                float p = __expf((t.x + t.y) * 0.125f);
                lsum[i] += p;
                Ps[(ty * 2 + i) * 68 + tx + 16 * j] = p;
            }
        }
        __syncthreads();

        // O += P V (k-pair over j; VsT d-major)
#pragma unroll
        for (int j4 = 0; j4 < 16; j4++) {
            ulonglong2 av[2];
#pragma unroll
            for (int i = 0; i < 2; i++) av[i] = P2[(ty * 2 + i) * 17 + j4];
#pragma unroll
            for (int j = 0; j < 4; j++) {
                ulonglong2 bv = V2[(tx + 16 * j) * 17 + j4];
#pragma unroll
                for (int i = 0; i < 2; i++) {
                    fma2(o2[i][j], av[i].x, bv.x);
                    fma2(o2[i][j], av[i].y, bv.y);
                }
            }
        }
        __syncthreads();   // Ks/VsT/Ps free for next iter
    }

    // one-time l reduction over the 16 tx lanes (same rows per half-warp)
#pragma unroll
    for (int i = 0; i < 2; i++) {
        float r = lsum[i];
        r += __shfl_xor_sync(0xffffffffu, r, 1);
        r += __shfl_xor_sync(0xffffffffu, r, 2);
        r += __shfl_xor_sync(0xffffffffu, r, 4);
        r += __shfl_xor_sync(0xffffffffu, r, 8);
        lsum[i] = 1.0f / r;
    }
#pragma unroll
    for (int i = 0; i < 2; i++) {
        const int row = b * S_ + qt * 32 + ty * 2 + i;
#pragma unroll
        for (int j = 0; j < 4; j++) {
            float2 t = unpk2(o2[i][j]);
            g_ctx[row * 64 + tx + 16 * j] = (t.x + t.y) * lsum[i];
        }
    }
}

// ---------------------------------------------------------------------------
// 3) Output projection (k-pair): out = ctx @ Weff + bo.
//    Block 64 rows x 128 cols, K=64 single pass, 256 threads, thread 8x4.
//    ty=tid>>5 (8) -> rows ty*8..+7 (warp = single row group -> pure-bc A);
//    tx=tid&31 -> cols m0 + tx + 32j.
// ---------------------------------------------------------------------------
#define OUT_SMEM_BYTES ((64*68 + 128*68) * 4)   // 52224

__global__ __launch_bounds__(256, 2) void outproj_kernel(float* __restrict__ out,
                                                         const float* __restrict__ bo)
{
    extern __shared__ float so[];
    float* Cs  = so;                  // [64][68]  natural [r][d]
    float* WsT = so + 64 * 68;        // [128][68] [m][d]

    const int tid = threadIdx.x;
    const int ty = tid >> 5;
    const int tx = tid & 31;
    const int r0 = blockIdx.x * 64;
    const int m0 = blockIdx.y * 128;

    float4* Cs4  = (float4*)Cs;
    float4* WsT4 = (float4*)WsT;
    const float4* Cg4 = (const float4*)(g_ctx + r0 * HD);
    const float4* Wg4 = (const float4*)(g_weffT + m0 * HD);

#pragma unroll
    for (int l = 0; l < 4; l++) {
        int i4 = tid + l * 256;
        Cs4[(i4 >> 4) * 17 + (i4 & 15)] = Cg4[i4];
    }
#pragma unroll
    for (int l = 0; l < 8; l++) {
        int i4 = tid + l * 256;
        WsT4[(i4 >> 4) * 17 + (i4 & 15)] = Wg4[i4];
    }
    __syncthreads();

    const ulonglong2* C2 = (const ulonglong2*)Cs;
    const ulonglong2* W2 = (const ulonglong2*)WsT;

    u64 acc[8][4];
#pragma unroll
    for (int i = 0; i < 8; i++)
#pragma unroll
        for (int j = 0; j < 4; j++) acc[i][j] = 0ull;

#pragma unroll
    for (int d4 = 0; d4 < 16; d4++) {
        ulonglong2 av[8];
#pragma unroll
        for (int i = 0; i < 8; i++) av[i] = C2[(ty * 8 + i) * 17 + d4];
#pragma unroll
        for (int j = 0; j < 4; j++) {
            ulonglong2 bv = W2[(tx + 32 * j) * 17 + d4];
#pragma unroll
            for (int i = 0; i < 8; i++) {
                fma2(acc[i][j], av[i].x, bv.x);
                fma2(acc[i][j], av[i].y, bv.y);
            }
        }
    }

    float bias_c[4];
#pragma unroll
    for (int j = 0; j < 4; j++) bias_c[j] = bo[m0 + tx + 32 * j];
#pragma unroll
    for (int i = 0; i < 8; i++) {
        const int row = r0 + ty * 8 + i;
#pragma unroll
        for (int j = 0; j < 4; j++) {
            float2 t = unpk2(acc[i][j]);
            out[row * DM + m0 + tx + 32 * j] = t.x + t.y + bias_c[j];
        }
    }
}

// ---------------------------------------------------------------------------
extern "C" void kernel_launch(void* const* d_in, const int* in_sizes, int n_in,
                              void* d_out, int out_size)
{
    (void)in_sizes; (void)n_in; (void)out_size;
    const float* query = (const float*)d_in[0];
    const float* key_  = (const float*)d_in[1];
    const float* value = (const float*)d_in[2];
    const float* Wq    = (const float*)d_in[3];
    const float* bq    = (const float*)d_in[4];
    const float* Wk    = (const float*)d_in[5];
    const float* bk    = (const float*)d_in[6];
    const float* Wv    = (const float*)d_in[7];
    const float* bv    = (const float*)d_in[8];
    const float* Wo    = (const float*)d_in[9];
    const float* bo    = (const float*)d_in[10];

    cudaFuncSetAttribute(qkv_kernel, cudaFuncAttributeMaxDynamicSharedMemorySize, QKV_SMEM_BYTES);
    cudaFuncSetAttribute(attn_kernel, cudaFuncAttributeMaxDynamicSharedMemorySize, ATTN_SMEM_BYTES);
    cudaFuncSetAttribute(outproj_kernel, cudaFuncAttributeMaxDynamicSharedMemorySize, OUT_SMEM_BYTES);

    prep_kernel<<<1024, 256>>>(Wq, Wk, Wv, Wo);
    qkv_kernel<<<dim3(128, 1, 3), 256, QKV_SMEM_BYTES>>>(query, key_, value, bq, bk, bv);
    attn_kernel<<<dim3(64, 8), 256, ATTN_SMEM_BYTES>>>();
    outproj_kernel<<<dim3(256, 8), 256, OUT_SMEM_BYTES>>>((float*)d_out, bo);
}

// round 13
// speedup vs baseline: 2.7750x; 2.7750x over previous
#include <cuda_runtime.h>
#include <cuda_bf16.h>
#include <cstdint>

// MultiHeadAttention_45732811768295 — R12: mma.sync bf16-split (sm_103-safe HMMA)

#define B_  8
#define S_  2048
#define DM  1024
#define HD  64
#define ROWS_TOT (B_ * S_)   // 16384
#define PLANE_BYTES ((size_t)ROWS_TOT * HD * 2)

typedef unsigned long long u64;

// ---------------- FFMA2 helpers (outproj) ----------------
__device__ __forceinline__ u64 pack2(float x, float y) {
    u64 r; asm("mov.b64 %0, {%1,%2};" : "=l"(r) : "f"(x), "f"(y)); return r;
}
__device__ __forceinline__ u64 dup2(float x) { return pack2(x, x); }
__device__ __forceinline__ void fma2(u64 &d, u64 a, u64 b) {
    asm("fma.rn.f32x2 %0, %1, %2, %0;" : "+l"(d) : "l"(a), "l"(b));
}
__device__ __forceinline__ float2 unpk2(u64 v) {
    float2 f; asm("mov.b64 {%0,%1}, %2;" : "=f"(f.x), "=f"(f.y) : "l"(v)); return f;
}

// ---------------- tensor-path helpers (baseline PTX, sm_80+) ----------------
__device__ __forceinline__ void cp16(uint32_t saddr, const void* g) {
    asm volatile("cp.async.cg.shared.global [%0], [%1], 16;" :: "r"(saddr), "l"(g));
}
#define CP_COMMIT() asm volatile("cp.async.commit_group;")
#define CP_WAIT1()  asm volatile("cp.async.wait_group 1;")
#define CP_WAIT0()  asm volatile("cp.async.wait_group 0;")

__device__ __forceinline__ void mma_bf16(float* d, const uint32_t* a, uint32_t b0, uint32_t b1) {
    asm volatile("mma.sync.aligned.m16n8k16.row.col.f32.bf16.bf16.f32 "
                 "{%0,%1,%2,%3}, {%4,%5,%6,%7}, {%8,%9}, {%0,%1,%2,%3};"
                 : "+f"(d[0]), "+f"(d[1]), "+f"(d[2]), "+f"(d[3])
                 : "r"(a[0]), "r"(a[1]), "r"(a[2]), "r"(a[3]), "r"(b0), "r"(b1));
}
__device__ __forceinline__ void ldsm4(uint32_t* r, uint32_t addr) {
    asm volatile("ldmatrix.sync.aligned.m8n8.x4.shared.b16 {%0,%1,%2,%3}, [%4];"
                 : "=r"(r[0]), "=r"(r[1]), "=r"(r[2]), "=r"(r[3]) : "r"(addr));
}
__device__ __forceinline__ void ldsm4t(uint32_t* r, uint32_t addr) {
    asm volatile("ldmatrix.sync.aligned.m8n8.x4.trans.shared.b16 {%0,%1,%2,%3}, [%4];"
                 : "=r"(r[0]), "=r"(r[1]), "=r"(r[2]), "=r"(r[3]) : "r"(addr));
}
__device__ __forceinline__ void sts32(uint32_t addr, uint32_t v) {
    asm volatile("st.shared.b32 [%0], %1;" :: "r"(addr), "r"(v) : "memory");
}
__device__ __forceinline__ void sts64(uint32_t addr, uint32_t v0, uint32_t v1) {
    asm volatile("st.shared.v2.b32 [%0], {%1,%2};" :: "r"(addr), "r"(v0), "r"(v1) : "memory");
}
// split (x0,x1) -> packed bf16x2 hi and residual lo (low half = x0)
__device__ __forceinline__ void split2(float x0, float x1, uint32_t& h, uint32_t& l) {
    asm("cvt.rn.bf16x2.f32 %0, %1, %2;" : "=r"(h) : "f"(x1), "f"(x0));
    float h0 = __uint_as_float(h << 16);
    float h1 = __uint_as_float(h & 0xffff0000u);
    asm("cvt.rn.bf16x2.f32 %0, %1, %2;" : "=r"(l) : "f"(x1 - h1), "f"(x0 - h0));
}

// ---------------- device scratch ----------------
__device__ __nv_bfloat16 g_qbf[2 * ROWS_TOT * HD];  // [hi/lo][row][d]
__device__ __nv_bfloat16 g_kbf[2 * ROWS_TOT * HD];
__device__ __nv_bfloat16 g_vbf[2 * ROWS_TOT * HD];
__device__ float g_ctx[ROWS_TOT * HD];
__device__ float g_weff[HD * DM];                   // [d][m]
__device__ __nv_bfloat16 g_wbf[3 * 2 * HD * DM];    // [w][hi/lo][n][k]

// ---------------------------------------------------------------------------
// 0) prep
// ---------------------------------------------------------------------------
__global__ void prep_kernel(const float* __restrict__ Wq, const float* __restrict__ Wk,
                            const float* __restrict__ Wv, const float* __restrict__ Wo)
{
    int idx = blockIdx.x * 256 + threadIdx.x;
    if (idx < 3 * HD * DM) {
        int w = idx >> 16;
        int r = idx & 0xFFFF;
        int j = r & 63;
        int k = r >> 6;
        const float* W = (w == 0) ? Wq : (w == 1) ? Wk : Wv;
        float x = W[k * HD + j];
        __nv_bfloat16 hi = __float2bfloat16(x);
        float hf = __bfloat162float(hi);
        __nv_bfloat16 lo = __float2bfloat16(x - hf);
        g_wbf[((w * 2 + 0) * HD + j) * DM + k] = hi;
        g_wbf[((w * 2 + 1) * HD + j) * DM + k] = lo;
    } else {
        int r = idx - 3 * HD * DM;
        int d = r >> 10, m = r & 1023;
        float s = 0.f;
#pragma unroll
        for (int h = 0; h < 16; h++) s += Wo[(h * 64 + d) * DM + m];
        g_weff[r] = s;
        (void)d; (void)m;
    }
}

// ---------------------------------------------------------------------------
// 1) QKV via mma.sync. Block 128x64, KC=32, 256 thr (warps 4m x 2n, warp 32x32).
// smem: A[buf][spl] 128 rows x 80B @ buf*20480 + spl*10240
//       B[buf][spl]  64 rows x 80B @ 40960 + buf*10240 + spl*5120
// ---------------------------------------------------------------------------
#define QKV_SMEM 61440

__global__ __launch_bounds__(256, 2) void qkv_mma_kernel(
    const float* __restrict__ in_q, const float* __restrict__ in_k, const float* __restrict__ in_v,
    const float* __restrict__ bq, const float* __restrict__ bk, const float* __restrict__ bv)
{
    extern __shared__ char sm[];
    const uint32_t sb = (uint32_t)__cvta_generic_to_shared(sm);
    const int tid = threadIdx.x, lane = tid & 31, wid = tid >> 5;
    const int wm = wid >> 1, wn = wid & 1;
    const int g = lane >> 2, t = lane & 3;

    const int w = blockIdx.y;
    const float* X    = (w == 0) ? in_q : (w == 1) ? in_k : in_v;
    const float* bias = (w == 0) ? bq   : (w == 1) ? bk   : bv;
    __nv_bfloat16* outp = (w == 0) ? g_qbf : (w == 1) ? g_kbf : g_vbf;
    const int rowBase = blockIdx.x * 128;

    const float4* X4 = (const float4*)X;
    const char* wh = (const char*)(g_wbf + (size_t)(2 * w) * HD * DM);
    const char* wl = wh + (size_t)HD * DM * 2;

    float2 bp[4];
#pragma unroll
    for (int nt = 0; nt < 4; nt++)
        bp[nt] = *(const float2*)&bias[wn * 32 + nt * 8 + 2 * t];

    auto produceA = [&](int kt, int buf) {
#pragma unroll
        for (int l = 0; l < 4; l++) {
            int i4 = tid + l * 256;               // 1024 = 128 rows x 8 f4
            int r = i4 >> 3, kq = i4 & 7;
            float4 x = X4[(size_t)(rowBase + r) * 256 + kt * 8 + kq];
            uint32_t h01, h23, l01, l23;
            split2(x.x, x.y, h01, l01);
            split2(x.z, x.w, h23, l23);
            uint32_t d = sb + buf * 20480 + r * 80 + kq * 8;
            sts64(d,         h01, h23);
            sts64(d + 10240, l01, l23);
        }
    };
    auto produceB = [&](int kt, int buf) {
        int n = tid >> 2, seg = tid & 3;          // 64 rows x 4 x 16B
        uint32_t dst = sb + 40960 + buf * 10240 + n * 80 + seg * 16;
        size_t src = (size_t)n * 2048 + (size_t)kt * 64 + seg * 16;
        cp16(dst,        wh + src);
        cp16(dst + 5120, wl + src);
    };

    produceA(0, 0); produceB(0, 0); CP_COMMIT();

    float acc[2][4][4];
#pragma unroll
    for (int i = 0; i < 2; i++)
#pragma unroll
        for (int j = 0; j < 4; j++)
#pragma unroll
            for (int e = 0; e < 4; e++) acc[i][j][e] = 0.f;

    const uint32_t aoff = (lane & 15) * 80 + (lane >> 4) * 16;  // A pattern
    const uint32_t boff = ((lane & 7) + ((lane >> 4) & 1) * 8) * 80 + ((lane >> 3) & 1) * 16;

    for (int kt = 0; kt < 32; kt++) {
        const int buf = kt & 1;
        if (kt + 1 < 32) { produceA(kt + 1, buf ^ 1); produceB(kt + 1, buf ^ 1); CP_COMMIT(); CP_WAIT1(); }
        else             { CP_WAIT0(); }
        __syncthreads();

        const uint32_t Ah = sb + buf * 20480, Al = Ah + 10240;
        const uint32_t Bh = sb + 40960 + buf * 10240, Bl = Bh + 5120;
#pragma unroll
        for (int ks = 0; ks < 2; ks++) {
            uint32_t ah[2][4], al[2][4], bh[2][4], bl[2][4];
#pragma unroll
            for (int mt = 0; mt < 2; mt++) {
                uint32_t ro = (wm * 32 + mt * 16) * 80 + ks * 32;
                ldsm4(ah[mt], Ah + ro + aoff);
                ldsm4(al[mt], Al + ro + aoff);
            }
#pragma unroll
            for (int p = 0; p < 2; p++) {
                uint32_t no = (wn * 32 + p * 16) * 80 + ks * 32;
                ldsm4(bh[p], Bh + no + boff);
                ldsm4(bl[p], Bl + no + boff);
            }
#pragma unroll
            for (int mt = 0; mt < 2; mt++)
#pragma unroll
                for (int nt = 0; nt < 4; nt++) {
                    int p = nt >> 1, q = (nt & 1) * 2;
                    mma_bf16(acc[mt][nt], ah[mt], bh[p][q], bh[p][q + 1]);
                    mma_bf16(acc[mt][nt], al[mt], bh[p][q], bh[p][q + 1]);
                    mma_bf16(acc[mt][nt], ah[mt], bl[p][q], bl[p][q + 1]);
                }
        }
        __syncthreads();
    }

    __nv_bfloat16* oh = outp;
    __nv_bfloat16* ol = outp + (size_t)ROWS_TOT * HD;
#pragma unroll
    for (int mt = 0; mt < 2; mt++)
#pragma unroll
        for (int nt = 0; nt < 4; nt++) {
            float* c = acc[mt][nt];
            int col = wn * 32 + nt * 8 + 2 * t;
            int r0 = rowBase + wm * 32 + mt * 16 + g;
            float d0 = c[0] + bp[nt].x, d1 = c[1] + bp[nt].y;
            float d2 = c[2] + bp[nt].x, d3 = c[3] + bp[nt].y;
            uint32_t h, l;
            split2(d0, d1, h, l);
            *(uint32_t*)(oh + (size_t)r0 * 64 + col) = h;
            *(uint32_t*)(ol + (size_t)r0 * 64 + col) = l;
            split2(d2, d3, h, l);
            *(uint32_t*)(oh + (size_t)(r0 + 8) * 64 + col) = h;
            *(uint32_t*)(ol + (size_t)(r0 + 8) * 64 + col) = l;
        }
}

// ---------------------------------------------------------------------------
// 2) Attention via mma.sync. q-tile 64, k-tile 64, 256 thr (warps 2m x 4n).
// smem (row stride 144B): Qh 0 / Ql 9216; K 18432+buf*18432+spl*9216;
//   V 55296+buf*18432+spl*9216; Ph 92160 / Pl 101376; lred 110592 (1KB).
// ---------------------------------------------------------------------------
#define ATTN_SMEM 111616

__global__ __launch_bounds__(256, 2) void attn_mma_kernel()
{
    extern __shared__ char sm[];
    const uint32_t sb = (uint32_t)__cvta_generic_to_shared(sm);
    const int tid = threadIdx.x, lane = tid & 31, wid = tid >> 5;
    const int wm = wid >> 2, wn = wid & 3;
    const int g = lane >> 2, t = lane & 3;
    const int b = blockIdx.y, qt = blockIdx.x;

    const char* qbf = (const char*)g_qbf;
    const char* kbf = (const char*)g_kbf;
    const char* vbf = (const char*)g_vbf;

#pragma unroll
    for (int l = 0; l < 2; l++) {
        int idx = tid + l * 256;                  // 512 = 64 rows x 8 segs
        int row = idx >> 3, seg = idx & 7;
        size_t src = (size_t)(b * S_ + qt * 64 + row) * 128 + seg * 16;
        cp16(sb + 0    + row * 144 + seg * 16, qbf + src);
        cp16(sb + 9216 + row * 144 + seg * 16, qbf + PLANE_BYTES + src);
    }
    auto produceKV = [&](int kt, int buf) {
#pragma unroll
        for (int l = 0; l < 2; l++) {
            int idx = tid + l * 256;
            int row = idx >> 3, seg = idx & 7;
            size_t src = (size_t)(b * S_ + kt * 64 + row) * 128 + seg * 16;
            uint32_t d = row * 144 + seg * 16;
            cp16(sb + 18432 + buf * 18432 + d,        kbf + src);
            cp16(sb + 18432 + buf * 18432 + 9216 + d, kbf + PLANE_BYTES + src);
            cp16(sb + 55296 + buf * 18432 + d,        vbf + src);
            cp16(sb + 55296 + buf * 18432 + 9216 + d, vbf + PLANE_BYTES + src);
        }
    };
    produceKV(0, 0); CP_COMMIT();

    float oacc[2][2][4];
    float lsum[4] = {0.f, 0.f, 0.f, 0.f};
#pragma unroll
    for (int i = 0; i < 2; i++)
#pragma unroll
        for (int j = 0; j < 2; j++)
#pragma unroll
            for (int e = 0; e < 4; e++) oacc[i][j][e] = 0.f;

    const uint32_t aoff = (lane & 15) * 144 + (lane >> 4) * 16;   // A / trans-B pattern
    const uint32_t boff = ((lane & 7) + ((lane >> 4) & 1) * 8) * 144 + ((lane >> 3) & 1) * 16;
    const uint32_t Ph = sb + 92160, Pl = Ph + 9216;

    for (int kt = 0; kt < 32; kt++) {
        const int buf = kt & 1;
        if (kt + 1 < 32) { produceKV(kt + 1, buf ^ 1); CP_COMMIT(); CP_WAIT1(); }
        else             { CP_WAIT0(); }
        __syncthreads();

        const uint32_t Qh = sb, Ql = sb + 9216;
        const uint32_t Kh = sb + 18432 + buf * 18432, Kl = Kh + 9216;
        const uint32_t Vh = sb + 55296 + buf * 18432, Vl = Vh + 9216;

        // ---- S = Q K^T (3-pass split) ----
        float sacc[2][2][4];
#pragma unroll
        for (int i = 0; i < 2; i++)
#pragma unroll
            for (int j = 0; j < 2; j++)
#pragma unroll
                for (int e = 0; e < 4; e++) sacc[i][j][e] = 0.f;

#pragma unroll
        for (int ks = 0; ks < 4; ks++) {
            uint32_t qh[2][4], ql[2][4], kh[4], kl[4];
#pragma unroll
            for (int mt = 0; mt < 2; mt++) {
                uint32_t ro = (wm * 32 + mt * 16) * 144 + ks * 32;
                ldsm4(qh[mt], Qh + ro + aoff);
                ldsm4(ql[mt], Ql + ro + aoff);
            }
            {
                uint32_t no = (wn * 16) * 144 + ks * 32;
                ldsm4(kh, Kh + no + boff);
                ldsm4(kl, Kl + no + boff);
            }
#pragma unroll
            for (int mt = 0; mt < 2; mt++)
#pragma unroll
                for (int nt = 0; nt < 2; nt++) {
                    mma_bf16(sacc[mt][nt], qh[mt], kh[2 * nt], kh[2 * nt + 1]);
                    mma_bf16(sacc[mt][nt], ql[mt], kh[2 * nt], kh[2 * nt + 1]);
                    mma_bf16(sacc[mt][nt], qh[mt], kl[2 * nt], kl[2 * nt + 1]);
                }
        }

        // ---- p = exp(s/8); accumulate row sums; split-store P ----
#pragma unroll
        for (int mt = 0; mt < 2; mt++)
#pragma unroll
            for (int nt = 0; nt < 2; nt++) {
                float* c = sacc[mt][nt];
                float p0 = __expf(c[0] * 0.125f), p1 = __expf(c[1] * 0.125f);
                float p2 = __expf(c[2] * 0.125f), p3 = __expf(c[3] * 0.125f);
                lsum[mt * 2 + 0] += p0 + p1;
                lsum[mt * 2 + 1] += p2 + p3;
                uint32_t cb = (wn * 16 + nt * 8 + 2 * t) * 2;
                uint32_t r0 = (wm * 32 + mt * 16 + g) * 144;
                uint32_t h, l;
                split2(p0, p1, h, l);
                sts32(Ph + r0 + cb, h);
                sts32(Pl + r0 + cb, l);
                split2(p2, p3, h, l);
                sts32(Ph + r0 + 8 * 144 + cb, h);
                sts32(Pl + r0 + 8 * 144 + cb, l);
            }
        __syncthreads();

        // ---- O += P V (V via ldmatrix.trans) ----
#pragma unroll
        for (int ks = 0; ks < 4; ks++) {
            uint32_t ph[2][4], pl[2][4], vh[4], vl[4];
#pragma unroll
            for (int mt = 0; mt < 2; mt++) {
                uint32_t ro = (wm * 32 + mt * 16) * 144 + ks * 32;
                ldsm4(ph[mt], Ph + ro + aoff);
                ldsm4(pl[mt], Pl + ro + aoff);
            }
            {
                uint32_t vo = (uint32_t)(ks * 16) * 144 + wn * 32;
                ldsm4t(vh, Vh + vo + aoff);
                ldsm4t(vl, Vl + vo + aoff);
            }
#pragma unroll
            for (int mt = 0; mt < 2; mt++)
#pragma unroll
                for (int nt = 0; nt < 2; nt++) {
                    mma_bf16(oacc[mt][nt], ph[mt], vh[2 * nt], vh[2 * nt + 1]);
                    mma_bf16(oacc[mt][nt], pl[mt], vh[2 * nt], vh[2 * nt + 1]);
                    mma_bf16(oacc[mt][nt], ph[mt], vl[2 * nt], vl[2 * nt + 1]);
                }
        }
        __syncthreads();
    }

    // ---- deferred l reduction ----
#pragma unroll
    for (int i = 0; i < 4; i++) {
        lsum[i] += __shfl_xor_sync(0xffffffffu, lsum[i], 1);
        lsum[i] += __shfl_xor_sync(0xffffffffu, lsum[i], 2);
    }
    float* lred = (float*)(sm + 110592);          // [4 nwarp][64 rows]
    if (t == 0) {
#pragma unroll
        for (int mt = 0; mt < 2; mt++) {
            lred[wn * 64 + wm * 32 + mt * 16 + g]     = lsum[mt * 2 + 0];
            lred[wn * 64 + wm * 32 + mt * 16 + g + 8] = lsum[mt * 2 + 1];
        }
    }
    __syncthreads();

#pragma unroll
    for (int mt = 0; mt < 2; mt++) {
        int ra = wm * 32 + mt * 16 + g;
        float ia = 1.f / (lred[ra] + lred[64 + ra] + lred[128 + ra] + lred[192 + ra]);
        float ib = 1.f / (lred[ra + 8] + lred[64 + ra + 8] + lred[128 + ra + 8] + lred[192 + ra + 8]);
#pragma unroll
        for (int nt = 0; nt < 2; nt++) {
            float* c = oacc[mt][nt];
            int col = wn * 16 + nt * 8 + 2 * t;
            size_t rowg = (size_t)(b * S_ + qt * 64 + ra);
            *(float2*)&g_ctx[rowg * 64 + col]       = make_float2(c[0] * ia, c[1] * ia);
            *(float2*)&g_ctx[(rowg + 8) * 64 + col] = make_float2(c[2] * ib, c[3] * ib);
        }
    }
}

// ---------------------------------------------------------------------------
// 3) Output projection (R5 dup-pack FFMA2, measured 48us)
// ---------------------------------------------------------------------------
#define OUTPROJ_SMEM_BYTES ((64*64 + 64*256) * 4)   // 81920

__global__ __launch_bounds__(256, 2) void outproj_kernel(float* __restrict__ out,
                                                         const float* __restrict__ bo)
{
    extern __shared__ float smo[];
    float* Cs = smo;
    float* Ws = smo + 64 * 64;

    const int tid = threadIdx.x;
    const int ty = tid >> 5;
    const int tx = tid & 31;
    const int r0 = blockIdx.x * 64;
    const int c4base = blockIdx.y * 64;

    float4* Cs4 = (float4*)Cs;
    float4* Ws4 = (float4*)Ws;
    const float4* Cg4 = (const float4*)(g_ctx + r0 * HD);
    const float4* Wg4 = (const float4*)g_weff;

#pragma unroll
    for (int l = 0; l < 4; l++) { int idx4 = tid + l * 256; Cs4[idx4] = Cg4[idx4]; }
#pragma unroll
    for (int l = 0; l < 16; l++) {
        int idx4 = tid + l * 256;
        int d = idx4 >> 6, c4 = idx4 & 63;
        Ws4[idx4] = Wg4[d * 256 + c4base + c4];
    }
    __syncthreads();

    u64 acc[8][4];
#pragma unroll
    for (int i = 0; i < 8; i++)
#pragma unroll
        for (int p = 0; p < 4; p++) acc[i][p] = 0ull;

#pragma unroll
    for (int d4 = 0; d4 < 16; d4++) {
        float4 a4[8];
#pragma unroll
        for (int i = 0; i < 8; i++) a4[i] = Cs4[(ty * 8 + i) * 16 + d4];
#pragma unroll
        for (int e = 0; e < 4; e++) {
            float4 b0 = Ws4[(d4 * 4 + e) * 64 + tx];
            float4 b1 = Ws4[(d4 * 4 + e) * 64 + 32 + tx];
            u64 b00 = pack2(b0.x, b0.y), b01 = pack2(b0.z, b0.w);
            u64 b10 = pack2(b1.x, b1.y), b11 = pack2(b1.z, b1.w);
#pragma unroll
            for (int i = 0; i < 8; i++) {
                float av = (e == 0) ? a4[i].x : (e == 1) ? a4[i].y : (e == 2) ? a4[i].z : a4[i].w;
                u64 ad = dup2(av);
                fma2(acc[i][0], ad, b00);
                fma2(acc[i][1], ad, b01);
                fma2(acc[i][2], ad, b10);
                fma2(acc[i][3], ad, b11);
            }
        }
    }

    const float4 bb0 = ((const float4*)bo)[c4base + tx];
    const float4 bb1 = ((const float4*)bo)[c4base + 32 + tx];
    float4* out4 = (float4*)out;
#pragma unroll
    for (int i = 0; i < 8; i++) {
        float2 q0 = unpk2(acc[i][0]);
        float2 q1 = unpk2(acc[i][1]);
        float2 q2 = unpk2(acc[i][2]);
        float2 q3 = unpk2(acc[i][3]);
        int row = r0 + ty * 8 + i;
        out4[row * 256 + c4base + tx] =
            make_float4(q0.x + bb0.x, q0.y + bb0.y, q1.x + bb0.z, q1.y + bb0.w);
        out4[row * 256 + c4base + 32 + tx] =
            make_float4(q2.x + bb1.x, q2.y + bb1.y, q3.x + bb1.z, q3.y + bb1.w);
    }
}

// ---------------------------------------------------------------------------
extern "C" void kernel_launch(void* const* d_in, const int* in_sizes, int n_in,
                              void* d_out, int out_size)
{
    (void)in_sizes; (void)n_in; (void)out_size;
    const float* query = (const float*)d_in[0];
    const float* key_  = (const float*)d_in[1];
    const float* value = (const float*)d_in[2];
    const float* Wq    = (const float*)d_in[3];
    const float* bq    = (const float*)d_in[4];
    const float* Wk    = (const float*)d_in[5];
    const float* bk    = (const float*)d_in[6];
    const float* Wv    = (const float*)d_in[7];
    const float* bv    = (const float*)d_in[8];
    const float* Wo    = (const float*)d_in[9];
    const float* bo    = (const float*)d_in[10];

    cudaFuncSetAttribute(qkv_mma_kernel, cudaFuncAttributeMaxDynamicSharedMemorySize, QKV_SMEM);
    cudaFuncSetAttribute(attn_mma_kernel, cudaFuncAttributeMaxDynamicSharedMemorySize, ATTN_SMEM);
    cudaFuncSetAttribute(outproj_kernel, cudaFuncAttributeMaxDynamicSharedMemorySize, OUTPROJ_SMEM_BYTES);

    prep_kernel<<<1024, 256>>>(Wq, Wk, Wv, Wo);
    qkv_mma_kernel<<<dim3(128, 3), 256, QKV_SMEM>>>(query, key_, value, bq, bk, bv);
    attn_mma_kernel<<<dim3(32, 8), 256, ATTN_SMEM>>>();
    outproj_kernel<<<dim3(256, 4), 256, OUTPROJ_SMEM_BYTES>>>((float*)d_out, bo);
}

// round 14
// speedup vs baseline: 3.0389x; 1.0951x over previous
#include <cuda_runtime.h>
#include <cuda_bf16.h>
#include <cstdint>

// MultiHeadAttention_45732811768295 — R13: all three GEMM stages on mma.sync
// bf16-split HMMA. ctx handed off as bf16 hi/lo planes; outproj tensorized.

#define B_  8
#define S_  2048
#define DM  1024
#define HD  64
#define ROWS_TOT (B_ * S_)   // 16384
#define PLANE_BYTES ((size_t)ROWS_TOT * HD * 2)

// ---------------- tensor-path helpers (baseline PTX, sm_80+) ----------------
__device__ __forceinline__ void cp16(uint32_t saddr, const void* g) {
    asm volatile("cp.async.cg.shared.global [%0], [%1], 16;" :: "r"(saddr), "l"(g));
}
#define CP_COMMIT() asm volatile("cp.async.commit_group;")
#define CP_WAIT1()  asm volatile("cp.async.wait_group 1;")
#define CP_WAIT0()  asm volatile("cp.async.wait_group 0;")

__device__ __forceinline__ void mma_bf16(float* d, const uint32_t* a, uint32_t b0, uint32_t b1) {
    asm volatile("mma.sync.aligned.m16n8k16.row.col.f32.bf16.bf16.f32 "
                 "{%0,%1,%2,%3}, {%4,%5,%6,%7}, {%8,%9}, {%0,%1,%2,%3};"
                 : "+f"(d[0]), "+f"(d[1]), "+f"(d[2]), "+f"(d[3])
                 : "r"(a[0]), "r"(a[1]), "r"(a[2]), "r"(a[3]), "r"(b0), "r"(b1));
}
__device__ __forceinline__ void ldsm4(uint32_t* r, uint32_t addr) {
    asm volatile("ldmatrix.sync.aligned.m8n8.x4.shared.b16 {%0,%1,%2,%3}, [%4];"
                 : "=r"(r[0]), "=r"(r[1]), "=r"(r[2]), "=r"(r[3]) : "r"(addr));
}
__device__ __forceinline__ void ldsm4t(uint32_t* r, uint32_t addr) {
    asm volatile("ldmatrix.sync.aligned.m8n8.x4.trans.shared.b16 {%0,%1,%2,%3}, [%4];"
                 : "=r"(r[0]), "=r"(r[1]), "=r"(r[2]), "=r"(r[3]) : "r"(addr));
}
__device__ __forceinline__ void sts32(uint32_t addr, uint32_t v) {
    asm volatile("st.shared.b32 [%0], %1;" :: "r"(addr), "r"(v) : "memory");
}
__device__ __forceinline__ void sts64(uint32_t addr, uint32_t v0, uint32_t v1) {
    asm volatile("st.shared.v2.b32 [%0], {%1,%2};" :: "r"(addr), "r"(v0), "r"(v1) : "memory");
}
// split (x0,x1) -> packed bf16x2 hi and residual lo (low half = x0)
__device__ __forceinline__ void split2(float x0, float x1, uint32_t& h, uint32_t& l) {
    asm("cvt.rn.bf16x2.f32 %0, %1, %2;" : "=r"(h) : "f"(x1), "f"(x0));
    float h0 = __uint_as_float(h << 16);
    float h1 = __uint_as_float(h & 0xffff0000u);
    asm("cvt.rn.bf16x2.f32 %0, %1, %2;" : "=r"(l) : "f"(x1 - h1), "f"(x0 - h0));
}

// ---------------- device scratch ----------------
__device__ __nv_bfloat16 g_qbf[2 * ROWS_TOT * HD];   // [hi/lo][row][d]
__device__ __nv_bfloat16 g_kbf[2 * ROWS_TOT * HD];
__device__ __nv_bfloat16 g_vbf[2 * ROWS_TOT * HD];
__device__ __nv_bfloat16 g_ctxbf[2 * ROWS_TOT * HD]; // [hi/lo][row][d]
__device__ __nv_bfloat16 g_weffbf[2 * DM * HD];      // [hi/lo][m][d]
__device__ __nv_bfloat16 g_wbf[3 * 2 * HD * DM];     // [w][hi/lo][n][k]

// ---------------------------------------------------------------------------
// 0) prep: split Wq/Wk/Wv -> [n][k] planes; fold Wo over heads -> split [m][d].
// ---------------------------------------------------------------------------
__global__ void prep_kernel(const float* __restrict__ Wq, const float* __restrict__ Wk,
                            const float* __restrict__ Wv, const float* __restrict__ Wo)
{
    int idx = blockIdx.x * 256 + threadIdx.x;
    if (idx < 3 * HD * DM) {
        int w = idx >> 16;
        int r = idx & 0xFFFF;
        int j = r & 63;
        int k = r >> 6;
        const float* W = (w == 0) ? Wq : (w == 1) ? Wk : Wv;
        float x = W[k * HD + j];
        __nv_bfloat16 hi = __float2bfloat16(x);
        float hf = __bfloat162float(hi);
        __nv_bfloat16 lo = __float2bfloat16(x - hf);
        g_wbf[((w * 2 + 0) * HD + j) * DM + k] = hi;
        g_wbf[((w * 2 + 1) * HD + j) * DM + k] = lo;
    } else {
        int r = idx - 3 * HD * DM;        // [d][m], m fastest (coalesced Wo reads)
        int d = r >> 10, m = r & 1023;
        float s = 0.f;
#pragma unroll
        for (int h = 0; h < 16; h++) s += Wo[(h * 64 + d) * DM + m];
        __nv_bfloat16 hi = __float2bfloat16(s);
        float hf = __bfloat162float(hi);
        __nv_bfloat16 lo = __float2bfloat16(s - hf);
        g_weffbf[m * HD + d] = hi;
        g_weffbf[DM * HD + m * HD + d] = lo;
    }
}

// ---------------------------------------------------------------------------
// 1) QKV via mma.sync (unchanged from R12). Block 128x64, KC=32, 256 thr.
// ---------------------------------------------------------------------------
#define QKV_SMEM 61440

__global__ __launch_bounds__(256, 2) void qkv_mma_kernel(
    const float* __restrict__ in_q, const float* __restrict__ in_k, const float* __restrict__ in_v,
    const float* __restrict__ bq, const float* __restrict__ bk, const float* __restrict__ bv)
{
    extern __shared__ char sm[];
    const uint32_t sb = (uint32_t)__cvta_generic_to_shared(sm);
    const int tid = threadIdx.x, lane = tid & 31, wid = tid >> 5;
    const int wm = wid >> 1, wn = wid & 1;
    const int g = lane >> 2, t = lane & 3;

    const int w = blockIdx.y;
    const float* X    = (w == 0) ? in_q : (w == 1) ? in_k : in_v;
    const float* bias = (w == 0) ? bq   : (w == 1) ? bk   : bv;
    __nv_bfloat16* outp = (w == 0) ? g_qbf : (w == 1) ? g_kbf : g_vbf;
    const int rowBase = blockIdx.x * 128;

    const float4* X4 = (const float4*)X;
    const char* wh = (const char*)(g_wbf + (size_t)(2 * w) * HD * DM);
    const char* wl = wh + (size_t)HD * DM * 2;

    float2 bp[4];
#pragma unroll
    for (int nt = 0; nt < 4; nt++)
        bp[nt] = *(const float2*)&bias[wn * 32 + nt * 8 + 2 * t];

    auto produceA = [&](int kt, int buf) {
#pragma unroll
        for (int l = 0; l < 4; l++) {
            int i4 = tid + l * 256;
            int r = i4 >> 3, kq = i4 & 7;
            float4 x = X4[(size_t)(rowBase + r) * 256 + kt * 8 + kq];
            uint32_t h01, h23, l01, l23;
            split2(x.x, x.y, h01, l01);
            split2(x.z, x.w, h23, l23);
            uint32_t d = sb + buf * 20480 + r * 80 + kq * 8;
            sts64(d,         h01, h23);
            sts64(d + 10240, l01, l23);
        }
    };
    auto produceB = [&](int kt, int buf) {
        int n = tid >> 2, seg = tid & 3;
        uint32_t dst = sb + 40960 + buf * 10240 + n * 80 + seg * 16;
        size_t src = (size_t)n * 2048 + (size_t)kt * 64 + seg * 16;
        cp16(dst,        wh + src);
        cp16(dst + 5120, wl + src);
    };

    produceA(0, 0); produceB(0, 0); CP_COMMIT();

    float acc[2][4][4];
#pragma unroll
    for (int i = 0; i < 2; i++)
#pragma unroll
        for (int j = 0; j < 4; j++)
#pragma unroll
            for (int e = 0; e < 4; e++) acc[i][j][e] = 0.f;

    const uint32_t aoff = (lane & 15) * 80 + (lane >> 4) * 16;
    const uint32_t boff = ((lane & 7) + ((lane >> 4) & 1) * 8) * 80 + ((lane >> 3) & 1) * 16;

    for (int kt = 0; kt < 32; kt++) {
        const int buf = kt & 1;
        if (kt + 1 < 32) { produceA(kt + 1, buf ^ 1); produceB(kt + 1, buf ^ 1); CP_COMMIT(); CP_WAIT1(); }
        else             { CP_WAIT0(); }
        __syncthreads();

        const uint32_t Ah = sb + buf * 20480, Al = Ah + 10240;
        const uint32_t Bh = sb + 40960 + buf * 10240, Bl = Bh + 5120;
#pragma unroll
        for (int ks = 0; ks < 2; ks++) {
            uint32_t ah[2][4], al[2][4], bh[2][4], bl[2][4];
#pragma unroll
            for (int mt = 0; mt < 2; mt++) {
                uint32_t ro = (wm * 32 + mt * 16) * 80 + ks * 32;
                ldsm4(ah[mt], Ah + ro + aoff);
                ldsm4(al[mt], Al + ro + aoff);
            }
#pragma unroll
            for (int p = 0; p < 2; p++) {
                uint32_t no = (wn * 32 + p * 16) * 80 + ks * 32;
                ldsm4(bh[p], Bh + no + boff);
                ldsm4(bl[p], Bl + no + boff);
            }
#pragma unroll
            for (int mt = 0; mt < 2; mt++)
#pragma unroll
                for (int nt = 0; nt < 4; nt++) {
                    int p = nt >> 1, q = (nt & 1) * 2;
                    mma_bf16(acc[mt][nt], ah[mt], bh[p][q], bh[p][q + 1]);
                    mma_bf16(acc[mt][nt], al[mt], bh[p][q], bh[p][q + 1]);
                    mma_bf16(acc[mt][nt], ah[mt], bl[p][q], bl[p][q + 1]);
                }
        }
        __syncthreads();
    }

    __nv_bfloat16* oh = outp;
    __nv_bfloat16* ol = outp + (size_t)ROWS_TOT * HD;
#pragma unroll
    for (int mt = 0; mt < 2; mt++)
#pragma unroll
        for (int nt = 0; nt < 4; nt++) {
            float* c = acc[mt][nt];
            int col = wn * 32 + nt * 8 + 2 * t;
            int r0 = rowBase + wm * 32 + mt * 16 + g;
            float d0 = c[0] + bp[nt].x, d1 = c[1] + bp[nt].y;
            float d2 = c[2] + bp[nt].x, d3 = c[3] + bp[nt].y;
            uint32_t h, l;
            split2(d0, d1, h, l);
            *(uint32_t*)(oh + (size_t)r0 * 64 + col) = h;
            *(uint32_t*)(ol + (size_t)r0 * 64 + col) = l;
            split2(d2, d3, h, l);
            *(uint32_t*)(oh + (size_t)(r0 + 8) * 64 + col) = h;
            *(uint32_t*)(ol + (size_t)(r0 + 8) * 64 + col) = l;
        }
}

// ---------------------------------------------------------------------------
// 2) Attention via mma.sync (R12 mainloop; epilogue now emits bf16 hi/lo ctx).
// ---------------------------------------------------------------------------
#define ATTN_SMEM 111616

__global__ __launch_bounds__(256, 2) void attn_mma_kernel()
{
    extern __shared__ char sm[];
    const uint32_t sb = (uint32_t)__cvta_generic_to_shared(sm);
    const int tid = threadIdx.x, lane = tid & 31, wid = tid >> 5;
    const int wm = wid >> 2, wn = wid & 3;
    const int g = lane >> 2, t = lane & 3;
    const int b = blockIdx.y, qt = blockIdx.x;

    const char* qbf = (const char*)g_qbf;
    const char* kbf = (const char*)g_kbf;
    const char* vbf = (const char*)g_vbf;

#pragma unroll
    for (int l = 0; l < 2; l++) {
        int idx = tid + l * 256;
        int row = idx >> 3, seg = idx & 7;
        size_t src = (size_t)(b * S_ + qt * 64 + row) * 128 + seg * 16;
        cp16(sb + 0    + row * 144 + seg * 16, qbf + src);
        cp16(sb + 9216 + row * 144 + seg * 16, qbf + PLANE_BYTES + src);
    }
    auto produceKV = [&](int kt, int buf) {
#pragma unroll
        for (int l = 0; l < 2; l++) {
            int idx = tid + l * 256;
            int row = idx >> 3, seg = idx & 7;
            size_t src = (size_t)(b * S_ + kt * 64 + row) * 128 + seg * 16;
            uint32_t d = row * 144 + seg * 16;
            cp16(sb + 18432 + buf * 18432 + d,        kbf + src);
            cp16(sb + 18432 + buf * 18432 + 9216 + d, kbf + PLANE_BYTES + src);
            cp16(sb + 55296 + buf * 18432 + d,        vbf + src);
            cp16(sb + 55296 + buf * 18432 + 9216 + d, vbf + PLANE_BYTES + src);
        }
    };
    produceKV(0, 0); CP_COMMIT();

    float oacc[2][2][4];
    float lsum[4] = {0.f, 0.f, 0.f, 0.f};
#pragma unroll
    for (int i = 0; i < 2; i++)
#pragma unroll
        for (int j = 0; j < 2; j++)
#pragma unroll
            for (int e = 0; e < 4; e++) oacc[i][j][e] = 0.f;

    const uint32_t aoff = (lane & 15) * 144 + (lane >> 4) * 16;
    const uint32_t boff = ((lane & 7) + ((lane >> 4) & 1) * 8) * 144 + ((lane >> 3) & 1) * 16;
    const uint32_t Ph = sb + 92160, Pl = Ph + 9216;

    for (int kt = 0; kt < 32; kt++) {
        const int buf = kt & 1;
        if (kt + 1 < 32) { produceKV(kt + 1, buf ^ 1); CP_COMMIT(); CP_WAIT1(); }
        else             { CP_WAIT0(); }
        __syncthreads();

        const uint32_t Qh = sb, Ql = sb + 9216;
        const uint32_t Kh = sb + 18432 + buf * 18432, Kl = Kh + 9216;
        const uint32_t Vh = sb + 55296 + buf * 18432, Vl = Vh + 9216;

        float sacc[2][2][4];
#pragma unroll
        for (int i = 0; i < 2; i++)
#pragma unroll
            for (int j = 0; j < 2; j++)
#pragma unroll
                for (int e = 0; e < 4; e++) sacc[i][j][e] = 0.f;

#pragma unroll
        for (int ks = 0; ks < 4; ks++) {
            uint32_t qh[2][4], ql[2][4], kh[4], kl[4];
#pragma unroll
            for (int mt = 0; mt < 2; mt++) {
                uint32_t ro = (wm * 32 + mt * 16) * 144 + ks * 32;
                ldsm4(qh[mt], Qh + ro + aoff);
                ldsm4(ql[mt], Ql + ro + aoff);
            }
            {
                uint32_t no = (wn * 16) * 144 + ks * 32;
                ldsm4(kh, Kh + no + boff);
                ldsm4(kl, Kl + no + boff);
            }
#pragma unroll
            for (int mt = 0; mt < 2; mt++)
#pragma unroll
                for (int nt = 0; nt < 2; nt++) {
                    mma_bf16(sacc[mt][nt], qh[mt], kh[2 * nt], kh[2 * nt + 1]);
                    mma_bf16(sacc[mt][nt], ql[mt], kh[2 * nt], kh[2 * nt + 1]);
                    mma_bf16(sacc[mt][nt], qh[mt], kl[2 * nt], kl[2 * nt + 1]);
                }
        }

#pragma unroll
        for (int mt = 0; mt < 2; mt++)
#pragma unroll
            for (int nt = 0; nt < 2; nt++) {
                float* c = sacc[mt][nt];
                float p0 = __expf(c[0] * 0.125f), p1 = __expf(c[1] * 0.125f);
                float p2 = __expf(c[2] * 0.125f), p3 = __expf(c[3] * 0.125f);
                lsum[mt * 2 + 0] += p0 + p1;
                lsum[mt * 2 + 1] += p2 + p3;
                uint32_t cb = (wn * 16 + nt * 8 + 2 * t) * 2;
                uint32_t r0 = (wm * 32 + mt * 16 + g) * 144;
                uint32_t h, l;
                split2(p0, p1, h, l);
                sts32(Ph + r0 + cb, h);
                sts32(Pl + r0 + cb, l);
                split2(p2, p3, h, l);
                sts32(Ph + r0 + 8 * 144 + cb, h);
                sts32(Pl + r0 + 8 * 144 + cb, l);
            }
        __syncthreads();

#pragma unroll
        for (int ks = 0; ks < 4; ks++) {
            uint32_t ph[2][4], pl[2][4], vh[4], vl[4];
#pragma unroll
            for (int mt = 0; mt < 2; mt++) {
                uint32_t ro = (wm * 32 + mt * 16) * 144 + ks * 32;
                ldsm4(ph[mt], Ph + ro + aoff);
                ldsm4(pl[mt], Pl + ro + aoff);
            }
            {
                uint32_t vo = (uint32_t)(ks * 16) * 144 + wn * 32;
                ldsm4t(vh, Vh + vo + aoff);
                ldsm4t(vl, Vl + vo + aoff);
            }
#pragma unroll
            for (int mt = 0; mt < 2; mt++)
#pragma unroll
                for (int nt = 0; nt < 2; nt++) {
                    mma_bf16(oacc[mt][nt], ph[mt], vh[2 * nt], vh[2 * nt + 1]);
                    mma_bf16(oacc[mt][nt], pl[mt], vh[2 * nt], vh[2 * nt + 1]);
                    mma_bf16(oacc[mt][nt], ph[mt], vl[2 * nt], vl[2 * nt + 1]);
                }
        }
        __syncthreads();
    }

#pragma unroll
    for (int i = 0; i < 4; i++) {
        lsum[i] += __shfl_xor_sync(0xffffffffu, lsum[i], 1);
        lsum[i] += __shfl_xor_sync(0xffffffffu, lsum[i], 2);
    }
    float* lred = (float*)(sm + 110592);
    if (t == 0) {
#pragma unroll
        for (int mt = 0; mt < 2; mt++) {
            lred[wn * 64 + wm * 32 + mt * 16 + g]     = lsum[mt * 2 + 0];
            lred[wn * 64 + wm * 32 + mt * 16 + g + 8] = lsum[mt * 2 + 1];
        }
    }
    __syncthreads();

    __nv_bfloat16* ch = g_ctxbf;
    __nv_bfloat16* cl = g_ctxbf + (size_t)ROWS_TOT * HD;
#pragma unroll
    for (int mt = 0; mt < 2; mt++) {
        int ra = wm * 32 + mt * 16 + g;
        float ia = 1.f / (lred[ra] + lred[64 + ra] + lred[128 + ra] + lred[192 + ra]);
        float ib = 1.f / (lred[ra + 8] + lred[64 + ra + 8] + lred[128 + ra + 8] + lred[192 + ra + 8]);
#pragma unroll
        for (int nt = 0; nt < 2; nt++) {
            float* c = oacc[mt][nt];
            int col = wn * 16 + nt * 8 + 2 * t;
            size_t rowg = (size_t)(b * S_ + qt * 64 + ra);
            uint32_t h, l;
            split2(c[0] * ia, c[1] * ia, h, l);
            *(uint32_t*)(ch + rowg * 64 + col) = h;
            *(uint32_t*)(cl + rowg * 64 + col) = l;
            split2(c[2] * ib, c[3] * ib, h, l);
            *(uint32_t*)(ch + (rowg + 8) * 64 + col) = h;
            *(uint32_t*)(cl + (rowg + 8) * 64 + col) = l;
        }
    }
}

// ---------------------------------------------------------------------------
// 3) Output projection via mma.sync: out = ctx @ Weff + bo.
//    Block 128 rows x 128 cols, K=64 single pass, 256 thr (warps 4m x 2n,
//    warp 32x64). smem rows stride 144B: Ah 0 / Al 18432; Bh 36864 / Bl 55296.
// ---------------------------------------------------------------------------
#define OUT_SMEM 73728

__global__ __launch_bounds__(256, 2) void outproj_mma_kernel(float* __restrict__ out,
                                                             const float* __restrict__ bo)
{
    extern __shared__ char sm[];
    const uint32_t sb = (uint32_t)__cvta_generic_to_shared(sm);
    const int tid = threadIdx.x, lane = tid & 31, wid = tid >> 5;
    const int wm = wid >> 1, wn = wid & 1;
    const int g = lane >> 2, t = lane & 3;
    const int r0 = blockIdx.x * 128;
    const int m0 = blockIdx.y * 128;

    const char* ch = (const char*)g_ctxbf;
    const char* cl = ch + PLANE_BYTES;
    const char* wh = (const char*)g_weffbf;
    const char* wl = wh + (size_t)DM * HD * 2;

#pragma unroll
    for (int l = 0; l < 4; l++) {
        int idx = tid + l * 256;                 // 1024 = 128 rows x 8 segs
        int row = idx >> 3, seg = idx & 7;
        uint32_t d = row * 144 + seg * 16;
        size_t csrc = (size_t)(r0 + row) * 128 + seg * 16;
        size_t wsrc = (size_t)(m0 + row) * 128 + seg * 16;
        cp16(sb + 0     + d, ch + csrc);
        cp16(sb + 18432 + d, cl + csrc);
        cp16(sb + 36864 + d, wh + wsrc);
        cp16(sb + 55296 + d, wl + wsrc);
    }
    CP_COMMIT(); CP_WAIT0();
    __syncthreads();

    const uint32_t aoff = (lane & 15) * 144 + (lane >> 4) * 16;
    const uint32_t boff = ((lane & 7) + ((lane >> 4) & 1) * 8) * 144 + ((lane >> 3) & 1) * 16;

    float acc[2][8][4];
#pragma unroll
    for (int i = 0; i < 2; i++)
#pragma unroll
        for (int j = 0; j < 8; j++)
#pragma unroll
            for (int e = 0; e < 4; e++) acc[i][j][e] = 0.f;

#pragma unroll
    for (int ks = 0; ks < 4; ks++) {
        uint32_t ah[2][4], al[2][4];
#pragma unroll
        for (int mt = 0; mt < 2; mt++) {
            uint32_t ro = (wm * 32 + mt * 16) * 144 + ks * 32;
            ldsm4(ah[mt], sb + 0     + ro + aoff);
            ldsm4(al[mt], sb + 18432 + ro + aoff);
        }
#pragma unroll
        for (int p = 0; p < 4; p++) {            // 4 n16 groups -> 8 n8 tiles
            uint32_t bh[4], bl[4];
            uint32_t no = (wn * 64 + p * 16) * 144 + ks * 32;
            ldsm4(bh, sb + 36864 + no + boff);
            ldsm4(bl, sb + 55296 + no + boff);
#pragma unroll
            for (int mt = 0; mt < 2; mt++)
#pragma unroll
                for (int q = 0; q < 2; q++) {
                    int nt = p * 2 + q;
                    mma_bf16(acc[mt][nt], ah[mt], bh[2 * q], bh[2 * q + 1]);
                    mma_bf16(acc[mt][nt], al[mt], bh[2 * q], bh[2 * q + 1]);
                    mma_bf16(acc[mt][nt], ah[mt], bl[2 * q], bl[2 * q + 1]);
                }
        }
    }

#pragma unroll
    for (int mt = 0; mt < 2; mt++) {
        int row = r0 + wm * 32 + mt * 16 + g;
#pragma unroll
        for (int nt = 0; nt < 8; nt++) {
            float* c = acc[mt][nt];
            int col = m0 + wn * 64 + nt * 8 + 2 * t;
            float2 bb = *(const float2*)&bo[col];
            *(float2*)&out[(size_t)row * DM + col]       = make_float2(c[0] + bb.x, c[1] + bb.y);
            *(float2*)&out[(size_t)(row + 8) * DM + col] = make_float2(c[2] + bb.x, c[3] + bb.y);
        }
    }
}

// ---------------------------------------------------------------------------
extern "C" void kernel_launch(void* const* d_in, const int* in_sizes, int n_in,
                              void* d_out, int out_size)
{
    (void)in_sizes; (void)n_in; (void)out_size;
    const float* query = (const float*)d_in[0];
    const float* key_  = (const float*)d_in[1];
    const float* value = (const float*)d_in[2];
    const float* Wq    = (const float*)d_in[3];
    const float* bq    = (const float*)d_in[4];
    const float* Wk    = (const float*)d_in[5];
    const float* bk    = (const float*)d_in[6];
    const float* Wv    = (const float*)d_in[7];
    const float* bv    = (const float*)d_in[8];
    const float* Wo    = (const float*)d_in[9];
    const float* bo    = (const float*)d_in[10];

    cudaFuncSetAttribute(qkv_mma_kernel, cudaFuncAttributeMaxDynamicSharedMemorySize, QKV_SMEM);
    cudaFuncSetAttribute(attn_mma_kernel, cudaFuncAttributeMaxDynamicSharedMemorySize, ATTN_SMEM);
    cudaFuncSetAttribute(outproj_mma_kernel, cudaFuncAttributeMaxDynamicSharedMemorySize, OUT_SMEM);

    prep_kernel<<<1024, 256>>>(Wq, Wk, Wv, Wo);
    qkv_mma_kernel<<<dim3(128, 3), 256, QKV_SMEM>>>(query, key_, value, bq, bk, bv);
    attn_mma_kernel<<<dim3(32, 8), 256, ATTN_SMEM>>>();
    outproj_mma_kernel<<<dim3(128, 8), 256, OUT_SMEM>>>((float*)d_out, bo);
}

// round 15
// speedup vs baseline: 3.0940x; 1.0181x over previous
#include <cuda_runtime.h>
#include <cuda_bf16.h>
#include <cstdint>

// MultiHeadAttention_45732811768295 — R14: attn with hoisted Q frags (4m x 2n),
// P overlaid on Q smem, softmax scale folded into Q projection (ex2 path).

#define B_  8
#define S_  2048
#define DM  1024
#define HD  64
#define ROWS_TOT (B_ * S_)   // 16384
#define PLANE_BYTES ((size_t)ROWS_TOT * HD * 2)
#define QSCALE 0.18033688011112042f   // 0.125 * log2(e)

// ---------------- tensor-path helpers (baseline PTX, sm_80+) ----------------
__device__ __forceinline__ void cp16(uint32_t saddr, const void* g) {
    asm volatile("cp.async.cg.shared.global [%0], [%1], 16;" :: "r"(saddr), "l"(g));
}
#define CP_COMMIT() asm volatile("cp.async.commit_group;")
#define CP_WAIT1()  asm volatile("cp.async.wait_group 1;")
#define CP_WAIT0()  asm volatile("cp.async.wait_group 0;")

__device__ __forceinline__ void mma_bf16(float* d, const uint32_t* a, uint32_t b0, uint32_t b1) {
    asm volatile("mma.sync.aligned.m16n8k16.row.col.f32.bf16.bf16.f32 "
                 "{%0,%1,%2,%3}, {%4,%5,%6,%7}, {%8,%9}, {%0,%1,%2,%3};"
                 : "+f"(d[0]), "+f"(d[1]), "+f"(d[2]), "+f"(d[3])
                 : "r"(a[0]), "r"(a[1]), "r"(a[2]), "r"(a[3]), "r"(b0), "r"(b1));
}
__device__ __forceinline__ void ldsm4(uint32_t* r, uint32_t addr) {
    asm volatile("ldmatrix.sync.aligned.m8n8.x4.shared.b16 {%0,%1,%2,%3}, [%4];"
                 : "=r"(r[0]), "=r"(r[1]), "=r"(r[2]), "=r"(r[3]) : "r"(addr));
}
__device__ __forceinline__ void ldsm4t(uint32_t* r, uint32_t addr) {
    asm volatile("ldmatrix.sync.aligned.m8n8.x4.trans.shared.b16 {%0,%1,%2,%3}, [%4];"
                 : "=r"(r[0]), "=r"(r[1]), "=r"(r[2]), "=r"(r[3]) : "r"(addr));
}
__device__ __forceinline__ void sts32(uint32_t addr, uint32_t v) {
    asm volatile("st.shared.b32 [%0], %1;" :: "r"(addr), "r"(v) : "memory");
}
__device__ __forceinline__ void sts64(uint32_t addr, uint32_t v0, uint32_t v1) {
    asm volatile("st.shared.v2.b32 [%0], {%1,%2};" :: "r"(addr), "r"(v0), "r"(v1) : "memory");
}
__device__ __forceinline__ float ex2f(float x) {
    float r; asm("ex2.approx.f32 %0, %1;" : "=f"(r) : "f"(x)); return r;
}
// split (x0,x1) -> packed bf16x2 hi and residual lo (low half = x0)
__device__ __forceinline__ void split2(float x0, float x1, uint32_t& h, uint32_t& l) {
    asm("cvt.rn.bf16x2.f32 %0, %1, %2;" : "=r"(h) : "f"(x1), "f"(x0));
    float h0 = __uint_as_float(h << 16);
    float h1 = __uint_as_float(h & 0xffff0000u);
    asm("cvt.rn.bf16x2.f32 %0, %1, %2;" : "=r"(l) : "f"(x1 - h1), "f"(x0 - h0));
}

// ---------------- device scratch ----------------
__device__ __nv_bfloat16 g_qbf[2 * ROWS_TOT * HD];   // [hi/lo][row][d] (pre-scaled by QSCALE)
__device__ __nv_bfloat16 g_kbf[2 * ROWS_TOT * HD];
__device__ __nv_bfloat16 g_vbf[2 * ROWS_TOT * HD];
__device__ __nv_bfloat16 g_ctxbf[2 * ROWS_TOT * HD]; // [hi/lo][row][d]
__device__ __nv_bfloat16 g_weffbf[2 * DM * HD];      // [hi/lo][m][d]
__device__ __nv_bfloat16 g_wbf[3 * 2 * HD * DM];     // [w][hi/lo][n][k]

// ---------------------------------------------------------------------------
// 0) prep: split Wq/Wk/Wv -> [n][k] planes (Wq pre-scaled); fold Wo -> [m][d].
// ---------------------------------------------------------------------------
__global__ void prep_kernel(const float* __restrict__ Wq, const float* __restrict__ Wk,
                            const float* __restrict__ Wv, const float* __restrict__ Wo)
{
    int idx = blockIdx.x * 256 + threadIdx.x;
    if (idx < 3 * HD * DM) {
        int w = idx >> 16;
        int r = idx & 0xFFFF;
        int j = r & 63;
        int k = r >> 6;
        const float* W = (w == 0) ? Wq : (w == 1) ? Wk : Wv;
        float x = W[k * HD + j];
        if (w == 0) x *= QSCALE;
        __nv_bfloat16 hi = __float2bfloat16(x);
        float hf = __bfloat162float(hi);
        __nv_bfloat16 lo = __float2bfloat16(x - hf);
        g_wbf[((w * 2 + 0) * HD + j) * DM + k] = hi;
        g_wbf[((w * 2 + 1) * HD + j) * DM + k] = lo;
    } else {
        int r = idx - 3 * HD * DM;        // [d][m], m fastest
        int d = r >> 10, m = r & 1023;
        float s = 0.f;
#pragma unroll
        for (int h = 0; h < 16; h++) s += Wo[(h * 64 + d) * DM + m];
        __nv_bfloat16 hi = __float2bfloat16(s);
        float hf = __bfloat162float(hi);
        __nv_bfloat16 lo = __float2bfloat16(s - hf);
        g_weffbf[m * HD + d] = hi;
        g_weffbf[DM * HD + m * HD + d] = lo;
    }
}

// ---------------------------------------------------------------------------
// 1) QKV via mma.sync (R13; q bias scaled by QSCALE).
// ---------------------------------------------------------------------------
#define QKV_SMEM 61440

__global__ __launch_bounds__(256, 2) void qkv_mma_kernel(
    const float* __restrict__ in_q, const float* __restrict__ in_k, const float* __restrict__ in_v,
    const float* __restrict__ bq, const float* __restrict__ bk, const float* __restrict__ bv)
{
    extern __shared__ char sm[];
    const uint32_t sb = (uint32_t)__cvta_generic_to_shared(sm);
    const int tid = threadIdx.x, lane = tid & 31, wid = tid >> 5;
    const int wm = wid >> 1, wn = wid & 1;
    const int g = lane >> 2, t = lane & 3;

    const int w = blockIdx.y;
    const float* X    = (w == 0) ? in_q : (w == 1) ? in_k : in_v;
    const float* bias = (w == 0) ? bq   : (w == 1) ? bk   : bv;
    __nv_bfloat16* outp = (w == 0) ? g_qbf : (w == 1) ? g_kbf : g_vbf;
    const int rowBase = blockIdx.x * 128;
    const float bscale = (w == 0) ? QSCALE : 1.0f;

    const float4* X4 = (const float4*)X;
    const char* wh = (const char*)(g_wbf + (size_t)(2 * w) * HD * DM);
    const char* wl = wh + (size_t)HD * DM * 2;

    float2 bp[4];
#pragma unroll
    for (int nt = 0; nt < 4; nt++) {
        bp[nt] = *(const float2*)&bias[wn * 32 + nt * 8 + 2 * t];
        bp[nt].x *= bscale; bp[nt].y *= bscale;
    }

    auto produceA = [&](int kt, int buf) {
#pragma unroll
        for (int l = 0; l < 4; l++) {
            int i4 = tid + l * 256;
            int r = i4 >> 3, kq = i4 & 7;
            float4 x = X4[(size_t)(rowBase + r) * 256 + kt * 8 + kq];
            uint32_t h01, h23, l01, l23;
            split2(x.x, x.y, h01, l01);
            split2(x.z, x.w, h23, l23);
            uint32_t d = sb + buf * 20480 + r * 80 + kq * 8;
            sts64(d,         h01, h23);
            sts64(d + 10240, l01, l23);
        }
    };
    auto produceB = [&](int kt, int buf) {
        int n = tid >> 2, seg = tid & 3;
        uint32_t dst = sb + 40960 + buf * 10240 + n * 80 + seg * 16;
        size_t src = (size_t)n * 2048 + (size_t)kt * 64 + seg * 16;
        cp16(dst,        wh + src);
        cp16(dst + 5120, wl + src);
    };

    produceA(0, 0); produceB(0, 0); CP_COMMIT();

    float acc[2][4][4];
#pragma unroll
    for (int i = 0; i < 2; i++)
#pragma unroll
        for (int j = 0; j < 4; j++)
#pragma unroll
            for (int e = 0; e < 4; e++) acc[i][j][e] = 0.f;

    const uint32_t aoff = (lane & 15) * 80 + (lane >> 4) * 16;
    const uint32_t boff = ((lane & 7) + ((lane >> 4) & 1) * 8) * 80 + ((lane >> 3) & 1) * 16;

    for (int kt = 0; kt < 32; kt++) {
        const int buf = kt & 1;
        if (kt + 1 < 32) { produceA(kt + 1, buf ^ 1); produceB(kt + 1, buf ^ 1); CP_COMMIT(); CP_WAIT1(); }
        else             { CP_WAIT0(); }
        __syncthreads();

        const uint32_t Ah = sb + buf * 20480, Al = Ah + 10240;
        const uint32_t Bh = sb + 40960 + buf * 10240, Bl = Bh + 5120;
#pragma unroll
        for (int ks = 0; ks < 2; ks++) {
            uint32_t ah[2][4], al[2][4], bh[2][4], bl[2][4];
#pragma unroll
            for (int mt = 0; mt < 2; mt++) {
                uint32_t ro = (wm * 32 + mt * 16) * 80 + ks * 32;
                ldsm4(ah[mt], Ah + ro + aoff);
                ldsm4(al[mt], Al + ro + aoff);
            }
#pragma unroll
            for (int p = 0; p < 2; p++) {
                uint32_t no = (wn * 32 + p * 16) * 80 + ks * 32;
                ldsm4(bh[p], Bh + no + boff);
                ldsm4(bl[p], Bl + no + boff);
            }
#pragma unroll
            for (int mt = 0; mt < 2; mt++)
#pragma unroll
                for (int nt = 0; nt < 4; nt++) {
                    int p = nt >> 1, q = (nt & 1) * 2;
                    mma_bf16(acc[mt][nt], ah[mt], bh[p][q], bh[p][q + 1]);
                    mma_bf16(acc[mt][nt], al[mt], bh[p][q], bh[p][q + 1]);
                    mma_bf16(acc[mt][nt], ah[mt], bl[p][q], bl[p][q + 1]);
                }
        }
        __syncthreads();
    }

    __nv_bfloat16* oh = outp;
    __nv_bfloat16* ol = outp + (size_t)ROWS_TOT * HD;
#pragma unroll
    for (int mt = 0; mt < 2; mt++)
#pragma unroll
        for (int nt = 0; nt < 4; nt++) {
            float* c = acc[mt][nt];
            int col = wn * 32 + nt * 8 + 2 * t;
            int r0 = rowBase + wm * 32 + mt * 16 + g;
            float d0 = c[0] + bp[nt].x, d1 = c[1] + bp[nt].y;
            float d2 = c[2] + bp[nt].x, d3 = c[3] + bp[nt].y;
            uint32_t h, l;
            split2(d0, d1, h, l);
            *(uint32_t*)(oh + (size_t)r0 * 64 + col) = h;
            *(uint32_t*)(ol + (size_t)r0 * 64 + col) = l;
            split2(d2, d3, h, l);
            *(uint32_t*)(oh + (size_t)(r0 + 8) * 64 + col) = h;
            *(uint32_t*)(ol + (size_t)(r0 + 8) * 64 + col) = l;
        }
}

// ---------------------------------------------------------------------------
// 2) Attention: 4m x 2n warps, Q frags hoisted to regs, P overlaid on Q smem.
// smem (rows stride 144B): Q/P hi @0, lo @9216; K @18432+buf*18432 (+9216 lo);
//   V @55296+buf*18432 (+9216 lo); lred @92160 (512B).
// ---------------------------------------------------------------------------
#define ATTN_SMEM 92672

__global__ __launch_bounds__(256, 2) void attn_mma_kernel()
{
    extern __shared__ char sm[];
    const uint32_t sb = (uint32_t)__cvta_generic_to_shared(sm);
    const int tid = threadIdx.x, lane = tid & 31, wid = tid >> 5;
    const int wm = wid >> 1, wn = wid & 1;      // 4m x 2n
    const int g = lane >> 2, t = lane & 3;
    const int b = blockIdx.y, qt = blockIdx.x;

    const char* qbf = (const char*)g_qbf;
    const char* kbf = (const char*)g_kbf;
    const char* vbf = (const char*)g_vbf;

    // Q prologue (both planes) into [0, 18432)
#pragma unroll
    for (int l = 0; l < 2; l++) {
        int idx = tid + l * 256;
        int row = idx >> 3, seg = idx & 7;
        size_t src = (size_t)(b * S_ + qt * 64 + row) * 128 + seg * 16;
        cp16(sb + 0    + row * 144 + seg * 16, qbf + src);
        cp16(sb + 9216 + row * 144 + seg * 16, qbf + PLANE_BYTES + src);
    }
    auto produceKV = [&](int kt, int buf) {
#pragma unroll
        for (int l = 0; l < 2; l++) {
            int idx = tid + l * 256;
            int row = idx >> 3, seg = idx & 7;
            size_t src = (size_t)(b * S_ + kt * 64 + row) * 128 + seg * 16;
            uint32_t d = row * 144 + seg * 16;
            cp16(sb + 18432 + buf * 18432 + d,        kbf + src);
            cp16(sb + 18432 + buf * 18432 + 9216 + d, kbf + PLANE_BYTES + src);
            cp16(sb + 55296 + buf * 18432 + d,        vbf + src);
            cp16(sb + 55296 + buf * 18432 + 9216 + d, vbf + PLANE_BYTES + src);
        }
    };
    produceKV(0, 0); CP_COMMIT();

    float oacc[4][4];
    float lsum[2] = {0.f, 0.f};
#pragma unroll
    for (int j = 0; j < 4; j++)
#pragma unroll
        for (int e = 0; e < 4; e++) oacc[j][e] = 0.f;

    const uint32_t aoff = (lane & 15) * 144 + (lane >> 4) * 16;
    const uint32_t boff = ((lane & 7) + ((lane >> 4) & 1) * 8) * 144 + ((lane >> 3) & 1) * 16;
    const uint32_t Ph = sb, Pl = sb + 9216;     // overlaid on Q region

    uint32_t qh[4][4], ql[4][4];                // hoisted Q fragments (per ks)

    for (int kt = 0; kt < 32; kt++) {
        const int buf = kt & 1;
        if (kt + 1 < 32) { produceKV(kt + 1, buf ^ 1); CP_COMMIT(); CP_WAIT1(); }
        else             { CP_WAIT0(); }
        __syncthreads();

        if (kt == 0) {
            // one-time Q fragment load, then barrier before P overwrites Q smem
#pragma unroll
            for (int ks = 0; ks < 4; ks++) {
                uint32_t ro = (wm * 16) * 144 + ks * 32;
                ldsm4(qh[ks], sb + 0    + ro + aoff);
                ldsm4(ql[ks], sb + 9216 + ro + aoff);
            }
            __syncthreads();
        }

        const uint32_t Kh = sb + 18432 + buf * 18432, Kl = Kh + 9216;
        const uint32_t Vh = sb + 55296 + buf * 18432, Vl = Vh + 9216;

        // ---- S = Q K^T (3-pass split; Q from regs) ----
        float sacc[4][4];
#pragma unroll
        for (int j = 0; j < 4; j++)
#pragma unroll
            for (int e = 0; e < 4; e++) sacc[j][e] = 0.f;

#pragma unroll
        for (int ks = 0; ks < 4; ks++) {
            uint32_t kh[2][4], kl[2][4];
#pragma unroll
            for (int grp = 0; grp < 2; grp++) {
                uint32_t no = (wn * 32 + grp * 16) * 144 + ks * 32;
                ldsm4(kh[grp], Kh + no + boff);
                ldsm4(kl[grp], Kl + no + boff);
            }
#pragma unroll
            for (int grp = 0; grp < 2; grp++)
#pragma unroll
                for (int q = 0; q < 2; q++) {
                    int nt = grp * 2 + q;
                    mma_bf16(sacc[nt], qh[ks], kh[grp][2 * q], kh[grp][2 * q + 1]);
                    mma_bf16(sacc[nt], ql[ks], kh[grp][2 * q], kh[grp][2 * q + 1]);
                    mma_bf16(sacc[nt], qh[ks], kl[grp][2 * q], kl[grp][2 * q + 1]);
                }
        }

        // ---- p = ex2(s) (scale pre-folded into Q); row sums; split-store P ----
#pragma unroll
        for (int nt = 0; nt < 4; nt++) {
            float* c = sacc[nt];
            float p0 = ex2f(c[0]), p1 = ex2f(c[1]);
            float p2 = ex2f(c[2]), p3 = ex2f(c[3]);
            lsum[0] += p0 + p1;
            lsum[1] += p2 + p3;
            uint32_t cb = (wn * 32 + nt * 8 + 2 * t) * 2;
            uint32_t r0 = (wm * 16 + g) * 144;
            uint32_t h, l;
            split2(p0, p1, h, l);
            sts32(Ph + r0 + cb, h);
            sts32(Pl + r0 + cb, l);
            split2(p2, p3, h, l);
            sts32(Ph + r0 + 8 * 144 + cb, h);
            sts32(Pl + r0 + 8 * 144 + cb, l);
        }
        __syncthreads();

        // ---- O += P V (V via ldmatrix.trans) ----
#pragma unroll
        for (int ks = 0; ks < 4; ks++) {
            uint32_t ph[4], pl[4], vh[2][4], vl[2][4];
            {
                uint32_t ro = (wm * 16) * 144 + ks * 32;
                ldsm4(ph, Ph + ro + aoff);
                ldsm4(pl, Pl + ro + aoff);
            }
#pragma unroll
            for (int grp = 0; grp < 2; grp++) {
                uint32_t vo = (uint32_t)(ks * 16) * 144 + wn * 64 + grp * 32;
                ldsm4t(vh[grp], Vh + vo + aoff);
                ldsm4t(vl[grp], Vl + vo + aoff);
            }
#pragma unroll
            for (int grp = 0; grp < 2; grp++)
#pragma unroll
                for (int q = 0; q < 2; q++) {
                    int nt = grp * 2 + q;
                    mma_bf16(oacc[nt], ph, vh[grp][2 * q], vh[grp][2 * q + 1]);
                    mma_bf16(oacc[nt], pl, vh[grp][2 * q], vh[grp][2 * q + 1]);
                    mma_bf16(oacc[nt], ph, vl[grp][2 * q], vl[grp][2 * q + 1]);
                }
        }
        __syncthreads();
    }

    // ---- deferred l reduction: t lanes, then the 2 n-warp groups ----
    lsum[0] += __shfl_xor_sync(0xffffffffu, lsum[0], 1);
    lsum[0] += __shfl_xor_sync(0xffffffffu, lsum[0], 2);
    lsum[1] += __shfl_xor_sync(0xffffffffu, lsum[1], 1);
    lsum[1] += __shfl_xor_sync(0xffffffffu, lsum[1], 2);
    float* lred = (float*)(sm + 92160);           // [2 nwarp][64 rows]
    int ra = wm * 16 + g;
    if (t == 0) {
        lred[wn * 64 + ra]     = lsum[0];
        lred[wn * 64 + ra + 8] = lsum[1];
    }
    __syncthreads();

    __nv_bfloat16* ch = g_ctxbf;
    __nv_bfloat16* cl = g_ctxbf + (size_t)ROWS_TOT * HD;
    float ia = 1.f / (lred[ra] + lred[64 + ra]);
    float ib = 1.f / (lred[ra + 8] + lred[64 + ra + 8]);
#pragma unroll
    for (int nt = 0; nt < 4; nt++) {
        float* c = oacc[nt];
        int col = wn * 32 + nt * 8 + 2 * t;
        size_t rowg = (size_t)(b * S_ + qt * 64 + ra);
        uint32_t h, l;
        split2(c[0] * ia, c[1] * ia, h, l);
        *(uint32_t*)(ch + rowg * 64 + col) = h;
        *(uint32_t*)(cl + rowg * 64 + col) = l;
        split2(c[2] * ib, c[3] * ib, h, l);
        *(uint32_t*)(ch + (rowg + 8) * 64 + col) = h;
        *(uint32_t*)(cl + (rowg + 8) * 64 + col) = l;
    }
}

// ---------------------------------------------------------------------------
// 3) Output projection via mma.sync (R13): out = ctx @ Weff + bo.
// ---------------------------------------------------------------------------
#define OUT_SMEM 73728

__global__ __launch_bounds__(256, 2) void outproj_mma_kernel(float* __restrict__ out,
                                                             const float* __restrict__ bo)
{
    extern __shared__ char sm[];
    const uint32_t sb = (uint32_t)__cvta_generic_to_shared(sm);
    const int tid = threadIdx.x, lane = tid & 31, wid = tid >> 5;
    const int wm = wid >> 1, wn = wid & 1;
    const int g = lane >> 2, t = lane & 3;
    const int r0 = blockIdx.x * 128;
    const int m0 = blockIdx.y * 128;

    const char* ch = (const char*)g_ctxbf;
    const char* cl = ch + PLANE_BYTES;
    const char* wh = (const char*)g_weffbf;
    const char* wl = wh + (size_t)DM * HD * 2;

#pragma unroll
    for (int l = 0; l < 4; l++) {
        int idx = tid + l * 256;
        int row = idx >> 3, seg = idx & 7;
        uint32_t d = row * 144 + seg * 16;
        size_t csrc = (size_t)(r0 + row) * 128 + seg * 16;
        size_t wsrc = (size_t)(m0 + row) * 128 + seg * 16;
        cp16(sb + 0     + d, ch + csrc);
        cp16(sb + 18432 + d, cl + csrc);
        cp16(sb + 36864 + d, wh + wsrc);
        cp16(sb + 55296 + d, wl + wsrc);
    }
    CP_COMMIT(); CP_WAIT0();
    __syncthreads();

    const uint32_t aoff = (lane & 15) * 144 + (lane >> 4) * 16;
    const uint32_t boff = ((lane & 7) + ((lane >> 4) & 1) * 8) * 144 + ((lane >> 3) & 1) * 16;

    float acc[2][8][4];
#pragma unroll
    for (int i = 0; i < 2; i++)
#pragma unroll
        for (int j = 0; j < 8; j++)
#pragma unroll
            for (int e = 0; e < 4; e++) acc[i][j][e] = 0.f;

#pragma unroll
    for (int ks = 0; ks < 4; ks++) {
        uint32_t ah[2][4], al[2][4];
#pragma unroll
        for (int mt = 0; mt < 2; mt++) {
            uint32_t ro = (wm * 32 + mt * 16) * 144 + ks * 32;
            ldsm4(ah[mt], sb + 0     + ro + aoff);
            ldsm4(al[mt], sb + 18432 + ro + aoff);
        }
#pragma unroll
        for (int p = 0; p < 4; p++) {
            uint32_t bh[4], bl[4];
            uint32_t no = (wn * 64 + p * 16) * 144 + ks * 32;
            ldsm4(bh, sb + 36864 + no + boff);
            ldsm4(bl, sb + 55296 + no + boff);
#pragma unroll
            for (int mt = 0; mt < 2; mt++)
#pragma unroll
                for (int q = 0; q < 2; q++) {
                    int nt = p * 2 + q;
                    mma_bf16(acc[mt][nt], ah[mt], bh[2 * q], bh[2 * q + 1]);
                    mma_bf16(acc[mt][nt], al[mt], bh[2 * q], bh[2 * q + 1]);
                    mma_bf16(acc[mt][nt], ah[mt], bl[2 * q], bl[2 * q + 1]);
                }
        }
    }

#pragma unroll
    for (int mt = 0; mt < 2; mt++) {
        int row = r0 + wm * 32 + mt * 16 + g;
#pragma unroll
        for (int nt = 0; nt < 8; nt++) {
            float* c = acc[mt][nt];
            int col = m0 + wn * 64 + nt * 8 + 2 * t;
            float2 bb = *(const float2*)&bo[col];
            *(float2*)&out[(size_t)row * DM + col]       = make_float2(c[0] + bb.x, c[1] + bb.y);
            *(float2*)&out[(size_t)(row + 8) * DM + col] = make_float2(c[2] + bb.x, c[3] + bb.y);
        }
    }
}

// ---------------------------------------------------------------------------
extern "C" void kernel_launch(void* const* d_in, const int* in_sizes, int n_in,
                              void* d_out, int out_size)
{
    (void)in_sizes; (void)n_in; (void)out_size;
    const float* query = (const float*)d_in[0];
    const float* key_  = (const float*)d_in[1];
    const float* value = (const float*)d_in[2];
    const float* Wq    = (const float*)d_in[3];
    const float* bq    = (const float*)d_in[4];
    const float* Wk    = (const float*)d_in[5];
    const float* bk    = (const float*)d_in[6];
    const float* Wv    = (const float*)d_in[7];
    const float* bv    = (const float*)d_in[8];
    const float* Wo    = (const float*)d_in[9];
    const float* bo    = (const float*)d_in[10];

    cudaFuncSetAttribute(qkv_mma_kernel, cudaFuncAttributeMaxDynamicSharedMemorySize, QKV_SMEM);
    cudaFuncSetAttribute(attn_mma_kernel, cudaFuncAttributeMaxDynamicSharedMemorySize, ATTN_SMEM);
    cudaFuncSetAttribute(outproj_mma_kernel, cudaFuncAttributeMaxDynamicSharedMemorySize, OUT_SMEM);

    prep_kernel<<<1024, 256>>>(Wq, Wk, Wv, Wo);
    qkv_mma_kernel<<<dim3(128, 3), 256, QKV_SMEM>>>(query, key_, value, bq, bk, bv);
    attn_mma_kernel<<<dim3(32, 8), 256, ATTN_SMEM>>>();
    outproj_mma_kernel<<<dim3(128, 8), 256, OUT_SMEM>>>((float*)d_out, bo);
}

// round 16
// speedup vs baseline: 3.1019x; 1.0026x over previous
#include <cuda_runtime.h>
#include <cuda_bf16.h>
#include <cstdint>

// MultiHeadAttention_45732811768295 — R15: non-volatile MMA + pass-major
// scheduling (accumulator reuse distance 4-8) to un-serialize the 3-pass split.

#define B_  8
#define S_  2048
#define DM  1024
#define HD  64
#define ROWS_TOT (B_ * S_)   // 16384
#define PLANE_BYTES ((size_t)ROWS_TOT * HD * 2)
#define QSCALE 0.18033688011112042f   // 0.125 * log2(e)

// ---------------- tensor-path helpers (baseline PTX, sm_80+) ----------------
__device__ __forceinline__ void cp16(uint32_t saddr, const void* g) {
    asm volatile("cp.async.cg.shared.global [%0], [%1], 16;" :: "r"(saddr), "l"(g));
}
#define CP_COMMIT() asm volatile("cp.async.commit_group;")
#define CP_WAIT1()  asm volatile("cp.async.wait_group 1;")
#define CP_WAIT0()  asm volatile("cp.async.wait_group 0;")

// NOTE: non-volatile on purpose — pure register op; lets ptxas pipeline MMAs.
__device__ __forceinline__ void mma_bf16(float* d, const uint32_t* a, uint32_t b0, uint32_t b1) {
    asm("mma.sync.aligned.m16n8k16.row.col.f32.bf16.bf16.f32 "
        "{%0,%1,%2,%3}, {%4,%5,%6,%7}, {%8,%9}, {%0,%1,%2,%3};"
        : "+f"(d[0]), "+f"(d[1]), "+f"(d[2]), "+f"(d[3])
        : "r"(a[0]), "r"(a[1]), "r"(a[2]), "r"(a[3]), "r"(b0), "r"(b1));
}
__device__ __forceinline__ void ldsm4(uint32_t* r, uint32_t addr) {
    asm volatile("ldmatrix.sync.aligned.m8n8.x4.shared.b16 {%0,%1,%2,%3}, [%4];"
                 : "=r"(r[0]), "=r"(r[1]), "=r"(r[2]), "=r"(r[3]) : "r"(addr));
}
__device__ __forceinline__ void ldsm4t(uint32_t* r, uint32_t addr) {
    asm volatile("ldmatrix.sync.aligned.m8n8.x4.trans.shared.b16 {%0,%1,%2,%3}, [%4];"
                 : "=r"(r[0]), "=r"(r[1]), "=r"(r[2]), "=r"(r[3]) : "r"(addr));
}
__device__ __forceinline__ void sts32(uint32_t addr, uint32_t v) {
    asm volatile("st.shared.b32 [%0], %1;" :: "r"(addr), "r"(v) : "memory");
}
__device__ __forceinline__ void sts64(uint32_t addr, uint32_t v0, uint32_t v1) {
    asm volatile("st.shared.v2.b32 [%0], {%1,%2};" :: "r"(addr), "r"(v0), "r"(v1) : "memory");
}
__device__ __forceinline__ float ex2f(float x) {
    float r; asm("ex2.approx.f32 %0, %1;" : "=f"(r) : "f"(x)); return r;
}
// split (x0,x1) -> packed bf16x2 hi and residual lo (low half = x0)
__device__ __forceinline__ void split2(float x0, float x1, uint32_t& h, uint32_t& l) {
    asm("cvt.rn.bf16x2.f32 %0, %1, %2;" : "=r"(h) : "f"(x1), "f"(x0));
    float h0 = __uint_as_float(h << 16);
    float h1 = __uint_as_float(h & 0xffff0000u);
    asm("cvt.rn.bf16x2.f32 %0, %1, %2;" : "=r"(l) : "f"(x1 - h1), "f"(x0 - h0));
}

// ---------------- device scratch ----------------
__device__ __nv_bfloat16 g_qbf[2 * ROWS_TOT * HD];   // [hi/lo][row][d] (pre-scaled)
__device__ __nv_bfloat16 g_kbf[2 * ROWS_TOT * HD];
__device__ __nv_bfloat16 g_vbf[2 * ROWS_TOT * HD];
__device__ __nv_bfloat16 g_ctxbf[2 * ROWS_TOT * HD];
__device__ __nv_bfloat16 g_weffbf[2 * DM * HD];      // [hi/lo][m][d]
__device__ __nv_bfloat16 g_wbf[3 * 2 * HD * DM];     // [w][hi/lo][n][k]

// ---------------------------------------------------------------------------
// 0) prep
// ---------------------------------------------------------------------------
__global__ void prep_kernel(const float* __restrict__ Wq, const float* __restrict__ Wk,
                            const float* __restrict__ Wv, const float* __restrict__ Wo)
{
    int idx = blockIdx.x * 256 + threadIdx.x;
    if (idx < 3 * HD * DM) {
        int w = idx >> 16;
        int r = idx & 0xFFFF;
        int j = r & 63;
        int k = r >> 6;
        const float* W = (w == 0) ? Wq : (w == 1) ? Wk : Wv;
        float x = W[k * HD + j];
        if (w == 0) x *= QSCALE;
        __nv_bfloat16 hi = __float2bfloat16(x);
        float hf = __bfloat162float(hi);
        __nv_bfloat16 lo = __float2bfloat16(x - hf);
        g_wbf[((w * 2 + 0) * HD + j) * DM + k] = hi;
        g_wbf[((w * 2 + 1) * HD + j) * DM + k] = lo;
    } else {
        int r = idx - 3 * HD * DM;
        int d = r >> 10, m = r & 1023;
        float s = 0.f;
#pragma unroll
        for (int h = 0; h < 16; h++) s += Wo[(h * 64 + d) * DM + m];
        __nv_bfloat16 hi = __float2bfloat16(s);
        float hf = __bfloat162float(hi);
        __nv_bfloat16 lo = __float2bfloat16(s - hf);
        g_weffbf[m * HD + d] = hi;
        g_weffbf[DM * HD + m * HD + d] = lo;
    }
}

// ---------------------------------------------------------------------------
// 1) QKV via mma.sync — pass-major MMA ordering (reuse distance 8).
// ---------------------------------------------------------------------------
#define QKV_SMEM 61440

__global__ __launch_bounds__(256, 2) void qkv_mma_kernel(
    const float* __restrict__ in_q, const float* __restrict__ in_k, const float* __restrict__ in_v,
    const float* __restrict__ bq, const float* __restrict__ bk, const float* __restrict__ bv)
{
    extern __shared__ char sm[];
    const uint32_t sb = (uint32_t)__cvta_generic_to_shared(sm);
    const int tid = threadIdx.x, lane = tid & 31, wid = tid >> 5;
    const int wm = wid >> 1, wn = wid & 1;
    const int g = lane >> 2, t = lane & 3;

    const int w = blockIdx.y;
    const float* X    = (w == 0) ? in_q : (w == 1) ? in_k : in_v;
    const float* bias = (w == 0) ? bq   : (w == 1) ? bk   : bv;
    __nv_bfloat16* outp = (w == 0) ? g_qbf : (w == 1) ? g_kbf : g_vbf;
    const int rowBase = blockIdx.x * 128;
    const float bscale = (w == 0) ? QSCALE : 1.0f;

    const float4* X4 = (const float4*)X;
    const char* wh = (const char*)(g_wbf + (size_t)(2 * w) * HD * DM);
    const char* wl = wh + (size_t)HD * DM * 2;

    float2 bp[4];
#pragma unroll
    for (int nt = 0; nt < 4; nt++) {
        bp[nt] = *(const float2*)&bias[wn * 32 + nt * 8 + 2 * t];
        bp[nt].x *= bscale; bp[nt].y *= bscale;
    }

    auto produceA = [&](int kt, int buf) {
#pragma unroll
        for (int l = 0; l < 4; l++) {
            int i4 = tid + l * 256;
            int r = i4 >> 3, kq = i4 & 7;
            float4 x = X4[(size_t)(rowBase + r) * 256 + kt * 8 + kq];
            uint32_t h01, h23, l01, l23;
            split2(x.x, x.y, h01, l01);
            split2(x.z, x.w, h23, l23);
            uint32_t d = sb + buf * 20480 + r * 80 + kq * 8;
            sts64(d,         h01, h23);
            sts64(d + 10240, l01, l23);
        }
    };
    auto produceB = [&](int kt, int buf) {
        int n = tid >> 2, seg = tid & 3;
        uint32_t dst = sb + 40960 + buf * 10240 + n * 80 + seg * 16;
        size_t src = (size_t)n * 2048 + (size_t)kt * 64 + seg * 16;
        cp16(dst,        wh + src);
        cp16(dst + 5120, wl + src);
    };

    produceA(0, 0); produceB(0, 0); CP_COMMIT();

    float acc[2][4][4];
#pragma unroll
    for (int i = 0; i < 2; i++)
#pragma unroll
        for (int j = 0; j < 4; j++)
#pragma unroll
            for (int e = 0; e < 4; e++) acc[i][j][e] = 0.f;

    const uint32_t aoff = (lane & 15) * 80 + (lane >> 4) * 16;
    const uint32_t boff = ((lane & 7) + ((lane >> 4) & 1) * 8) * 80 + ((lane >> 3) & 1) * 16;

    for (int kt = 0; kt < 32; kt++) {
        const int buf = kt & 1;
        if (kt + 1 < 32) { produceA(kt + 1, buf ^ 1); produceB(kt + 1, buf ^ 1); CP_COMMIT(); CP_WAIT1(); }
        else             { CP_WAIT0(); }
        __syncthreads();

        const uint32_t Ah = sb + buf * 20480, Al = Ah + 10240;
        const uint32_t Bh = sb + 40960 + buf * 10240, Bl = Bh + 5120;
#pragma unroll
        for (int ks = 0; ks < 2; ks++) {
            uint32_t ah[2][4], al[2][4], bh[2][4], bl[2][4];
#pragma unroll
            for (int mt = 0; mt < 2; mt++) {
                uint32_t ro = (wm * 32 + mt * 16) * 80 + ks * 32;
                ldsm4(ah[mt], Ah + ro + aoff);
                ldsm4(al[mt], Al + ro + aoff);
            }
#pragma unroll
            for (int p = 0; p < 2; p++) {
                uint32_t no = (wn * 32 + p * 16) * 80 + ks * 32;
                ldsm4(bh[p], Bh + no + boff);
                ldsm4(bl[p], Bl + no + boff);
            }
            // pass-major: 8 independent accs between reuses
#pragma unroll
            for (int mt = 0; mt < 2; mt++)
#pragma unroll
                for (int nt = 0; nt < 4; nt++) {
                    int p = nt >> 1, q = (nt & 1) * 2;
                    mma_bf16(acc[mt][nt], ah[mt], bh[p][q], bh[p][q + 1]);
                }
#pragma unroll
            for (int mt = 0; mt < 2; mt++)
#pragma unroll
                for (int nt = 0; nt < 4; nt++) {
                    int p = nt >> 1, q = (nt & 1) * 2;
                    mma_bf16(acc[mt][nt], al[mt], bh[p][q], bh[p][q + 1]);
                }
#pragma unroll
            for (int mt = 0; mt < 2; mt++)
#pragma unroll
                for (int nt = 0; nt < 4; nt++) {
                    int p = nt >> 1, q = (nt & 1) * 2;
                    mma_bf16(acc[mt][nt], ah[mt], bl[p][q], bl[p][q + 1]);
                }
        }
        __syncthreads();
    }

    __nv_bfloat16* oh = outp;
    __nv_bfloat16* ol = outp + (size_t)ROWS_TOT * HD;
#pragma unroll
    for (int mt = 0; mt < 2; mt++)
#pragma unroll
        for (int nt = 0; nt < 4; nt++) {
            float* c = acc[mt][nt];
            int col = wn * 32 + nt * 8 + 2 * t;
            int r0 = rowBase + wm * 32 + mt * 16 + g;
            float d0 = c[0] + bp[nt].x, d1 = c[1] + bp[nt].y;
            float d2 = c[2] + bp[nt].x, d3 = c[3] + bp[nt].y;
            uint32_t h, l;
            split2(d0, d1, h, l);
            *(uint32_t*)(oh + (size_t)r0 * 64 + col) = h;
            *(uint32_t*)(ol + (size_t)r0 * 64 + col) = l;
            split2(d2, d3, h, l);
            *(uint32_t*)(oh + (size_t)(r0 + 8) * 64 + col) = h;
            *(uint32_t*)(ol + (size_t)(r0 + 8) * 64 + col) = l;
        }
}

// ---------------------------------------------------------------------------
// 2) Attention — pass-major ordering; Q frags hoisted; P overlaid on Q smem.
// ---------------------------------------------------------------------------
#define ATTN_SMEM 92672

__global__ __launch_bounds__(256, 2) void attn_mma_kernel()
{
    extern __shared__ char sm[];
    const uint32_t sb = (uint32_t)__cvta_generic_to_shared(sm);
    const int tid = threadIdx.x, lane = tid & 31, wid = tid >> 5;
    const int wm = wid >> 1, wn = wid & 1;      // 4m x 2n
    const int g = lane >> 2, t = lane & 3;
    const int b = blockIdx.y, qt = blockIdx.x;

    const char* qbf = (const char*)g_qbf;
    const char* kbf = (const char*)g_kbf;
    const char* vbf = (const char*)g_vbf;

#pragma unroll
    for (int l = 0; l < 2; l++) {
        int idx = tid + l * 256;
        int row = idx >> 3, seg = idx & 7;
        size_t src = (size_t)(b * S_ + qt * 64 + row) * 128 + seg * 16;
        cp16(sb + 0    + row * 144 + seg * 16, qbf + src);
        cp16(sb + 9216 + row * 144 + seg * 16, qbf + PLANE_BYTES + src);
    }
    auto produceKV = [&](int kt, int buf) {
#pragma unroll
        for (int l = 0; l < 2; l++) {
            int idx = tid + l * 256;
            int row = idx >> 3, seg = idx & 7;
            size_t src = (size_t)(b * S_ + kt * 64 + row) * 128 + seg * 16;
            uint32_t d = row * 144 + seg * 16;
            cp16(sb + 18432 + buf * 18432 + d,        kbf + src);
            cp16(sb + 18432 + buf * 18432 + 9216 + d, kbf + PLANE_BYTES + src);
            cp16(sb + 55296 + buf * 18432 + d,        vbf + src);
            cp16(sb + 55296 + buf * 18432 + 9216 + d, vbf + PLANE_BYTES + src);
        }
    };
    produceKV(0, 0); CP_COMMIT();

    float oacc[4][4];
    float lsum[2] = {0.f, 0.f};
#pragma unroll
    for (int j = 0; j < 4; j++)
#pragma unroll
        for (int e = 0; e < 4; e++) oacc[j][e] = 0.f;

    const uint32_t aoff = (lane & 15) * 144 + (lane >> 4) * 16;
    const uint32_t boff = ((lane & 7) + ((lane >> 4) & 1) * 8) * 144 + ((lane >> 3) & 1) * 16;
    const uint32_t Ph = sb, Pl = sb + 9216;

    uint32_t qh[4][4], ql[4][4];

    for (int kt = 0; kt < 32; kt++) {
        const int buf = kt & 1;
        if (kt + 1 < 32) { produceKV(kt + 1, buf ^ 1); CP_COMMIT(); CP_WAIT1(); }
        else             { CP_WAIT0(); }
        __syncthreads();

        if (kt == 0) {
#pragma unroll
            for (int ks = 0; ks < 4; ks++) {
                uint32_t ro = (wm * 16) * 144 + ks * 32;
                ldsm4(qh[ks], sb + 0    + ro + aoff);
                ldsm4(ql[ks], sb + 9216 + ro + aoff);
            }
            __syncthreads();
        }

        const uint32_t Kh = sb + 18432 + buf * 18432, Kl = Kh + 9216;
        const uint32_t Vh = sb + 55296 + buf * 18432, Vl = Vh + 9216;

        // ---- S = Q K^T ----
        float sacc[4][4];
#pragma unroll
        for (int j = 0; j < 4; j++)
#pragma unroll
            for (int e = 0; e < 4; e++) sacc[j][e] = 0.f;

#pragma unroll
        for (int ks = 0; ks < 4; ks++) {
            uint32_t kh[2][4], kl[2][4];
#pragma unroll
            for (int grp = 0; grp < 2; grp++) {
                uint32_t no = (wn * 32 + grp * 16) * 144 + ks * 32;
                ldsm4(kh[grp], Kh + no + boff);
                ldsm4(kl[grp], Kl + no + boff);
            }
            // pass-major over 4 accs
#pragma unroll
            for (int nt = 0; nt < 4; nt++)
                mma_bf16(sacc[nt], qh[ks], kh[nt >> 1][(nt & 1) * 2], kh[nt >> 1][(nt & 1) * 2 + 1]);
#pragma unroll
            for (int nt = 0; nt < 4; nt++)
                mma_bf16(sacc[nt], ql[ks], kh[nt >> 1][(nt & 1) * 2], kh[nt >> 1][(nt & 1) * 2 + 1]);
#pragma unroll
            for (int nt = 0; nt < 4; nt++)
                mma_bf16(sacc[nt], qh[ks], kl[nt >> 1][(nt & 1) * 2], kl[nt >> 1][(nt & 1) * 2 + 1]);
        }

        // ---- p = ex2(s); row sums; split-store P ----
#pragma unroll
        for (int nt = 0; nt < 4; nt++) {
            float* c = sacc[nt];
            float p0 = ex2f(c[0]), p1 = ex2f(c[1]);
            float p2 = ex2f(c[2]), p3 = ex2f(c[3]);
            lsum[0] += p0 + p1;
            lsum[1] += p2 + p3;
            uint32_t cb = (wn * 32 + nt * 8 + 2 * t) * 2;
            uint32_t r0 = (wm * 16 + g) * 144;
            uint32_t h, l;
            split2(p0, p1, h, l);
            sts32(Ph + r0 + cb, h);
            sts32(Pl + r0 + cb, l);
            split2(p2, p3, h, l);
            sts32(Ph + r0 + 8 * 144 + cb, h);
            sts32(Pl + r0 + 8 * 144 + cb, l);
        }
        __syncthreads();

        // ---- O += P V ----
#pragma unroll
        for (int ks = 0; ks < 4; ks++) {
            uint32_t ph[4], pl[4], vh[2][4], vl[2][4];
            {
                uint32_t ro = (wm * 16) * 144 + ks * 32;
                ldsm4(ph, Ph + ro + aoff);
                ldsm4(pl, Pl + ro + aoff);
            }
#pragma unroll
            for (int grp = 0; grp < 2; grp++) {
                uint32_t vo = (uint32_t)(ks * 16) * 144 + wn * 64 + grp * 32;
                ldsm4t(vh[grp], Vh + vo + aoff);
                ldsm4t(vl[grp], Vl + vo + aoff);
            }
#pragma unroll
            for (int nt = 0; nt < 4; nt++)
                mma_bf16(oacc[nt], ph, vh[nt >> 1][(nt & 1) * 2], vh[nt >> 1][(nt & 1) * 2 + 1]);
#pragma unroll
            for (int nt = 0; nt < 4; nt++)
                mma_bf16(oacc[nt], pl, vh[nt >> 1][(nt & 1) * 2], vh[nt >> 1][(nt & 1) * 2 + 1]);
#pragma unroll
            for (int nt = 0; nt < 4; nt++)
                mma_bf16(oacc[nt], ph, vl[nt >> 1][(nt & 1) * 2], vl[nt >> 1][(nt & 1) * 2 + 1]);
        }
        __syncthreads();
    }

    // ---- deferred l reduction ----
    lsum[0] += __shfl_xor_sync(0xffffffffu, lsum[0], 1);
    lsum[0] += __shfl_xor_sync(0xffffffffu, lsum[0], 2);
    lsum[1] += __shfl_xor_sync(0xffffffffu, lsum[1], 1);
    lsum[1] += __shfl_xor_sync(0xffffffffu, lsum[1], 2);
    float* lred = (float*)(sm + 92160);
    int ra = wm * 16 + g;
    if (t == 0) {
        lred[wn * 64 + ra]     = lsum[0];
        lred[wn * 64 + ra + 8] = lsum[1];
    }
    __syncthreads();

    __nv_bfloat16* ch = g_ctxbf;
    __nv_bfloat16* cl = g_ctxbf + (size_t)ROWS_TOT * HD;
    float ia = 1.f / (lred[ra] + lred[64 + ra]);
    float ib = 1.f / (lred[ra + 8] + lred[64 + ra + 8]);
#pragma unroll
    for (int nt = 0; nt < 4; nt++) {
        float* c = oacc[nt];
        int col = wn * 32 + nt * 8 + 2 * t;
        size_t rowg = (size_t)(b * S_ + qt * 64 + ra);
        uint32_t h, l;
        split2(c[0] * ia, c[1] * ia, h, l);
        *(uint32_t*)(ch + rowg * 64 + col) = h;
        *(uint32_t*)(cl + rowg * 64 + col) = l;
        split2(c[2] * ib, c[3] * ib, h, l);
        *(uint32_t*)(ch + (rowg + 8) * 64 + col) = h;
        *(uint32_t*)(cl + (rowg + 8) * 64 + col) = l;
    }
}

// ---------------------------------------------------------------------------
// 3) Output projection — pass-major within each p group (reuse distance 4).
// ---------------------------------------------------------------------------
#define OUT_SMEM 73728

__global__ __launch_bounds__(256, 2) void outproj_mma_kernel(float* __restrict__ out,
                                                             const float* __restrict__ bo)
{
    extern __shared__ char sm[];
    const uint32_t sb = (uint32_t)__cvta_generic_to_shared(sm);
    const int tid = threadIdx.x, lane = tid & 31, wid = tid >> 5;
    const int wm = wid >> 1, wn = wid & 1;
    const int g = lane >> 2, t = lane & 3;
    const int r0 = blockIdx.x * 128;
    const int m0 = blockIdx.y * 128;

    const char* ch = (const char*)g_ctxbf;
    const char* cl = ch + PLANE_BYTES;
    const char* wh = (const char*)g_weffbf;
    const char* wl = wh + (size_t)DM * HD * 2;

#pragma unroll
    for (int l = 0; l < 4; l++) {
        int idx = tid + l * 256;
        int row = idx >> 3, seg = idx & 7;
        uint32_t d = row * 144 + seg * 16;
        size_t csrc = (size_t)(r0 + row) * 128 + seg * 16;
        size_t wsrc = (size_t)(m0 + row) * 128 + seg * 16;
        cp16(sb + 0     + d, ch + csrc);
        cp16(sb + 18432 + d, cl + csrc);
        cp16(sb + 36864 + d, wh + wsrc);
        cp16(sb + 55296 + d, wl + wsrc);
    }
    CP_COMMIT(); CP_WAIT0();
    __syncthreads();

    const uint32_t aoff = (lane & 15) * 144 + (lane >> 4) * 16;
    const uint32_t boff = ((lane & 7) + ((lane >> 4) & 1) * 8) * 144 + ((lane >> 3) & 1) * 16;

    float acc[2][8][4];
#pragma unroll
    for (int i = 0; i < 2; i++)
#pragma unroll
        for (int j = 0; j < 8; j++)
#pragma unroll
            for (int e = 0; e < 4; e++) acc[i][j][e] = 0.f;

#pragma unroll
    for (int ks = 0; ks < 4; ks++) {
        uint32_t ah[2][4], al[2][4];
#pragma unroll
        for (int mt = 0; mt < 2; mt++) {
            uint32_t ro = (wm * 32 + mt * 16) * 144 + ks * 32;
            ldsm4(ah[mt], sb + 0     + ro + aoff);
            ldsm4(al[mt], sb + 18432 + ro + aoff);
        }
#pragma unroll
        for (int p = 0; p < 4; p++) {
            uint32_t bh[4], bl[4];
            uint32_t no = (wn * 64 + p * 16) * 144 + ks * 32;
            ldsm4(bh, sb + 36864 + no + boff);
            ldsm4(bl, sb + 55296 + no + boff);
            // pass-major over the 4 (mt,q) accs of this p group
#pragma unroll
            for (int mt = 0; mt < 2; mt++)
#pragma unroll
                for (int q = 0; q < 2; q++)
                    mma_bf16(acc[mt][p * 2 + q], ah[mt], bh[2 * q], bh[2 * q + 1]);
#pragma unroll
            for (int mt = 0; mt < 2; mt++)
#pragma unroll
                for (int q = 0; q < 2; q++)
                    mma_bf16(acc[mt][p * 2 + q], al[mt], bh[2 * q], bh[2 * q + 1]);
#pragma unroll
            for (int mt = 0; mt < 2; mt++)
#pragma unroll
                for (int q = 0; q < 2; q++)
                    mma_bf16(acc[mt][p * 2 + q], ah[mt], bl[2 * q], bl[2 * q + 1]);
        }
    }

#pragma unroll
    for (int mt = 0; mt < 2; mt++) {
        int row = r0 + wm * 32 + mt * 16 + g;
#pragma unroll
        for (int nt = 0; nt < 8; nt++) {
            float* c = acc[mt][nt];
            int col = m0 + wn * 64 + nt * 8 + 2 * t;
            float2 bb = *(const float2*)&bo[col];
            *(float2*)&out[(size_t)row * DM + col]       = make_float2(c[0] + bb.x, c[1] + bb.y);
            *(float2*)&out[(size_t)(row + 8) * DM + col] = make_float2(c[2] + bb.x, c[3] + bb.y);
        }
    }
}

// ---------------------------------------------------------------------------
extern "C" void kernel_launch(void* const* d_in, const int* in_sizes, int n_in,
                              void* d_out, int out_size)
{
    (void)in_sizes; (void)n_in; (void)out_size;
    const float* query = (const float*)d_in[0];
    const float* key_  = (const float*)d_in[1];
    const float* value = (const float*)d_in[2];
    const float* Wq    = (const float*)d_in[3];
    const float* bq    = (const float*)d_in[4];
    const float* Wk    = (const float*)d_in[5];
    const float* bk    = (const float*)d_in[6];
    const float* Wv    = (const float*)d_in[7];
    const float* bv    = (const float*)d_in[8];
    const float* Wo    = (const float*)d_in[9];
    const float* bo    = (const float*)d_in[10];

    cudaFuncSetAttribute(qkv_mma_kernel, cudaFuncAttributeMaxDynamicSharedMemorySize, QKV_SMEM);
    cudaFuncSetAttribute(attn_mma_kernel, cudaFuncAttributeMaxDynamicSharedMemorySize, ATTN_SMEM);
    cudaFuncSetAttribute(outproj_mma_kernel, cudaFuncAttributeMaxDynamicSharedMemorySize, OUT_SMEM);

    prep_kernel<<<1024, 256>>>(Wq, Wk, Wv, Wo);
    qkv_mma_kernel<<<dim3(128, 3), 256, QKV_SMEM>>>(query, key_, value, bq, bk, bv);
    attn_mma_kernel<<<dim3(32, 8), 256, ATTN_SMEM>>>();
    outproj_mma_kernel<<<dim3(128, 8), 256, OUT_SMEM>>>((float*)d_out, bo);
}